// round 10
// baseline (speedup 1.0000x reference)
#include <cuda_runtime.h>
#include <cuda_bf16.h>
#include <cuda_fp16.h>
#include <cstdint>

#define TT 512
#define BB 256
#define HH 1024
#define KK 1024

// ---------------- device globals (static scratch; no allocations) ----------
__device__ __align__(16) unsigned short g_xhi[TT*BB*HH];   // 256MB
__device__ __align__(16) unsigned short g_xlo[TT*BB*HH];   // 256MB
__device__ __align__(16) unsigned short g_hhi[2][BB*HH];
__device__ __align__(16) unsigned short g_hlo[2][BB*HH];
__device__ unsigned g_count4[4 * 32];   // one counter per bt group, 128B apart
__device__ unsigned g_gen4[4 * 32];

// ---------------- helpers ---------------------------------------------------
__device__ __forceinline__ uint32_t smem_u32(const void* p) {
    uint32_t a;
    asm("{ .reg .u64 t; cvta.to.shared.u64 t, %1; cvt.u32.u64 %0, t; }"
        : "=r"(a) : "l"(p));
    return a;
}

__device__ __forceinline__ void ldsm4(uint32_t* r, uint32_t addr) {
    asm volatile("ldmatrix.sync.aligned.m8n8.x4.shared.b16 {%0,%1,%2,%3}, [%4];"
        : "=r"(r[0]), "=r"(r[1]), "=r"(r[2]), "=r"(r[3]) : "r"(addr));
}

// fp16 MMA
__device__ __forceinline__ void mma16816h(float* c, const uint32_t* a, const uint32_t* b) {
    asm volatile("mma.sync.aligned.m16n8k16.row.col.f32.f16.f16.f32 "
        "{%0,%1,%2,%3}, {%4,%5,%6,%7}, {%8,%9}, {%0,%1,%2,%3};"
        : "+f"(c[0]), "+f"(c[1]), "+f"(c[2]), "+f"(c[3])
        : "r"(a[0]), "r"(a[1]), "r"(a[2]), "r"(a[3]), "r"(b[0]), "r"(b[1]));
}

#define CP16(dst, src) \
    asm volatile("{\n\t.reg .u64 g;\n\tcvta.to.global.u64 g, %1;\n\t" \
                 "cp.async.cg.shared.global [%0], [g], 16;\n\t}" \
                 :: "r"(dst), "l"(src) : "memory")
#define CP_COMMIT() asm volatile("cp.async.commit_group;" ::: "memory")
#define CP_WAITN(n) asm volatile("cp.async.wait_group %0;" :: "n"(n) : "memory")

__device__ __forceinline__ float tanh_fast(float x) {
    float e = __expf(2.0f * x);
    return 1.0f - 2.0f / (e + 1.0f);
}

// fp16 split
__device__ __forceinline__ void split2h(float a, float b, uint32_t& hi, uint32_t& lo) {
    __half ha = __float2half_rn(a);
    __half hb = __float2half_rn(b);
    float ra = a - __half2float(ha);
    float rb = b - __half2float(hb);
    __half la = __float2half_rn(ra);
    __half lb = __float2half_rn(rb);
    hi = (uint32_t)__half_as_ushort(ha) | ((uint32_t)__half_as_ushort(hb) << 16);
    lo = (uint32_t)__half_as_ushort(la) | ((uint32_t)__half_as_ushort(lb) << 16);
}

// fp16 pack (hi only)
__device__ __forceinline__ uint32_t pack2h(float a, float b) {
    __half ha = __float2half_rn(a);
    __half hb = __float2half_rn(b);
    return (uint32_t)__half_as_ushort(ha) | ((uint32_t)__half_as_ushort(hb) << 16);
}

// per-bt-group barrier: 32 participating blocks
__device__ __forceinline__ void group_sync(unsigned* cntp, unsigned* genp,
                                           unsigned base, unsigned gen) {
    __syncthreads();
    if (threadIdx.x == 0) {
        const unsigned target = base + gen;
        __threadfence();
        unsigned a = atomicAdd(cntp, 1u);
        if (a == 31u) {
            *(volatile unsigned*)cntp = 0u;
            __threadfence();
            atomicExch(genp, target);
        } else {
            while ((int)(*(volatile unsigned*)genp - target) < 0) __nanosleep(32);
        }
        __threadfence();
    }
    __syncthreads();
}

// ---------------------------------------------------------------------------
// Prep: split x (fp32) into fp16 hi/lo device arrays. One pass, ~1GB traffic.
// ---------------------------------------------------------------------------
__global__ void xsplit_kernel(const float* __restrict__ X)
{
    size_t i = (size_t)blockIdx.x * 256 + threadIdx.x;   // float4 index
    float4 v = ((const float4*)X)[i];
    uint2 hi, lo;
    split2h(v.x, v.y, hi.x, lo.x);
    split2h(v.z, v.w, hi.y, lo.y);
    ((uint2*)g_xhi)[i] = hi;
    ((uint2*)g_xlo)[i] = lo;
}

// ---------------------------------------------------------------------------
// Fused persistent RNN: h_t = tanh(x_t@Wx^T + h_{t-1}@Wh^T + bx + bh).
// 128 blocks = 4 bt(64 rows) x 32 jt(32 cols). 256 threads = 8 warps,
// warp tile 16m x 16n, full k=1024 per warp (no kg split, no partial
// exchange). Wh_hi + Wx_hi resident in smem (2064B padded rows). Per step:
// 16 chunks of k64, 3-stage cp.async pipeline of 4 A streams
// (h_hi, h_lo, x_hi, x_lo). 2-term fp16 for both products.
// ---------------------------------------------------------------------------
#define P2_NBLK 128
#define WH_OFF  0
#define WX_OFF  66048
#define A_OFF   132096            // + stage*32768; streams at +0/8192/16384/24576
#define P2_SMEM 230400

__global__ void __launch_bounds__(256, 1)
rnn_fused(const float* __restrict__ Wh, const float* __restrict__ Wx,
          const float* __restrict__ bx, const float* __restrict__ bh,
          float* __restrict__ out)
{
    extern __shared__ char smem[];
    __shared__ float bsum[32];
    __shared__ unsigned sbase;
    const uint32_t sb = smem_u32(smem);
    const int tid = threadIdx.x;
    const int lane = tid & 31;
    const int w = tid >> 5;
    const int wm = w >> 1;           // 0..3 (16 m rows each)
    const int wn = w & 1;            // 0..1 (16 n cols each)
    const int bidx = blockIdx.x;
    const int jt = bidx & 31, bt = bidx >> 5;
    const int j0 = jt * 32, b0 = bt * 64;

    unsigned* cntp = &g_count4[bt * 32];
    unsigned* genp = &g_gen4[bt * 32];

    float* hfinal = out;
    float* hall = out + (size_t)BB * HH;

    if (tid == 0) sbase = *(volatile unsigned*)genp;
    if (tid < 32) bsum[tid] = bx[j0 + tid] + bh[j0 + tid];

    // resident W tiles (fp16 hi only): 32 j-rows x 1024 k, rows padded 2064B
#pragma unroll 1
    for (int i = tid; i < 32 * 256; i += 256) {
        int row = i >> 8, k4 = i & 255;
        uint32_t off = (uint32_t)(row * 2064 + k4 * 8);
        float4 vh = *(const float4*)(Wh + (size_t)(j0 + row) * KK + k4 * 4);
        uint2 hp;
        hp.x = pack2h(vh.x, vh.y);
        hp.y = pack2h(vh.z, vh.w);
        *(uint2*)(smem + WH_OFF + off) = hp;
        float4 vx = *(const float4*)(Wx + (size_t)(j0 + row) * KK + k4 * 4);
        hp.x = pack2h(vx.x, vx.y);
        hp.y = pack2h(vx.z, vx.w);
        *(uint2*)(smem + WX_OFF + off) = hp;
    }

    // zero this bt group's t=0 hidden-state rows (32 blocks share the slice)
    {
        uint4 z = make_uint4(0, 0, 0, 0);
        const int sliceBase = b0 * HH / 8;      // uint4 index of row b0
        for (int i = jt * 256 + tid; i < 64 * HH / 8; i += 32 * 256) {
            ((uint4*)g_hhi[0])[sliceBase + i] = z;
            ((uint4*)g_hlo[0])[sliceBase + i] = z;
        }
    }
    __syncthreads();
    const unsigned base = sbase;
    unsigned gen = 1;
    group_sync(cntp, genp, base, gen++);

    // ldmatrix A addressing (swizzled 128B rows)
    const uint32_t aLin = (uint32_t)((wm * 16 + (lane & 15)) * 128 + (lane >> 4) * 16);
    const uint32_t aXor = (uint32_t)((lane & 7) << 4);
    // ldmatrix B addressing (2064B padded rows, resident W)
    const uint32_t bRel = (uint32_t)((wn * 16 + ((lane >> 4) & 1) * 8 + (lane & 7)) * 2064
                                     + ((lane >> 3) & 1) * 16);
    // cp.async coords: rows (tid>>3) and (tid>>3)+32, seg tid&7
    const int cprow = tid >> 3, cpseg = tid & 7;
    const uint32_t aBase = sb + A_OFF;

    // epilogue fragment coordinates
    int erow[2], ecol[2];
#pragma unroll
    for (int p = 0; p < 2; ++p) erow[p] = wm * 16 + (lane >> 2) + p * 8;
#pragma unroll
    for (int ni = 0; ni < 2; ++ni) ecol[ni] = wn * 16 + ni * 8 + (lane & 3) * 2;

#pragma unroll 1
    for (int t = 0; t < TT; ++t) {
        const unsigned short* hrh = g_hhi[t & 1];
        const unsigned short* hrl = g_hlo[t & 1];
        unsigned short* hwh = g_hhi[(t & 1) ^ 1];
        unsigned short* hwl = g_hlo[(t & 1) ^ 1];
        const unsigned short* xh = g_xhi + (size_t)t * (BB * HH);
        const unsigned short* xl = g_xlo + (size_t)t * (BB * HH);
        float* hat = hall + (size_t)t * (BB * HH);

        float cc[2][4];
#pragma unroll
        for (int b = 0; b < 2; ++b)
#pragma unroll
            for (int q = 0; q < 4; ++q) cc[b][q] = 0.0f;

        // prologue: issue chunks 0 and 1
#pragma unroll
        for (int pc = 0; pc < 2; ++pc) {
            const uint32_t stg = aBase + (uint32_t)(pc * 32768);
#pragma unroll
            for (int j = 0; j < 2; ++j) {
                int row = cprow + 32 * j;
                uint32_t off = (((uint32_t)(row * 128 + cpseg * 16)) ^ ((uint32_t)(row & 7) << 4));
                size_t src = (size_t)(b0 + row) * KK + pc * 64 + cpseg * 8;
                CP16(stg + off,         hrh + src);
                CP16(stg + 8192 + off,  hrl + src);
                CP16(stg + 16384 + off, xh + src);
                CP16(stg + 24576 + off, xl + src);
            }
            CP_COMMIT();
        }

#pragma unroll 1
        for (int c = 0; c < 16; ++c) {
            if (c < 15) { CP_WAITN(1); } else { CP_WAITN(0); }
            __syncthreads();
            if (c + 2 < 16) {
                const uint32_t stg = aBase + (uint32_t)(((c + 2) % 3) * 32768);
#pragma unroll
                for (int j = 0; j < 2; ++j) {
                    int row = cprow + 32 * j;
                    uint32_t off = (((uint32_t)(row * 128 + cpseg * 16)) ^ ((uint32_t)(row & 7) << 4));
                    size_t src = (size_t)(b0 + row) * KK + (c + 2) * 64 + cpseg * 8;
                    CP16(stg + off,         hrh + src);
                    CP16(stg + 8192 + off,  hrl + src);
                    CP16(stg + 16384 + off, xh + src);
                    CP16(stg + 24576 + off, xl + src);
                }
                CP_COMMIT();
            }

            const uint32_t stg = aBase + (uint32_t)((c % 3) * 32768);
            const uint32_t kOff = (uint32_t)(c * 128);   // byte offset in W rows
#pragma unroll
            for (int kk = 0; kk < 4; ++kk) {
                const uint32_t ka = kk * 32;
                const uint32_t aoff = (aLin + ka) ^ aXor;
                uint32_t ah[4], al[4], axh[4], axl[4], bhf[4], bxf[4];
                ldsm4(ah,  stg + aoff);
                ldsm4(al,  stg + 8192 + aoff);
                ldsm4(axh, stg + 16384 + aoff);
                ldsm4(axl, stg + 24576 + aoff);
                ldsm4(bhf, sb + WH_OFF + bRel + kOff + ka);
                ldsm4(bxf, sb + WX_OFF + bRel + kOff + ka);
#pragma unroll
                for (int ni = 0; ni < 2; ++ni) {
                    mma16816h(cc[ni], ah,  bhf + 2 * ni);
                    mma16816h(cc[ni], al,  bhf + 2 * ni);
                    mma16816h(cc[ni], axh, bxf + 2 * ni);
                    mma16816h(cc[ni], axl, bxf + 2 * ni);
                }
            }
        }

        // epilogue: all 256 threads own their 16x16 fragment piece
#pragma unroll
        for (int ni = 0; ni < 2; ++ni)
#pragma unroll
            for (int p = 0; p < 2; ++p) {
                const int col = ecol[ni];
                size_t idx = (size_t)(b0 + erow[p]) * HH + j0 + col;
                float v0 = tanh_fast(cc[ni][2 * p]     + bsum[col]);
                float v1 = tanh_fast(cc[ni][2 * p + 1] + bsum[col + 1]);
                *(float2*)(hat + idx) = make_float2(v0, v1);
                if (t == TT - 1) *(float2*)(hfinal + idx) = make_float2(v0, v1);
                uint32_t hi, lo;
                split2h(v0, v1, hi, lo);
                *(uint32_t*)(hwh + idx) = hi;
                *(uint32_t*)(hwl + idx) = lo;
            }

        group_sync(cntp, genp, base, gen++);
    }
}

// ---------------------------------------------------------------------------
extern "C" void kernel_launch(void* const* d_in, const int* in_sizes, int n_in,
                              void* d_out, int out_size)
{
    (void)in_sizes; (void)n_in; (void)out_size;
    const float* x  = (const float*)d_in[0];
    const float* Wx = (const float*)d_in[1];
    const float* bx = (const float*)d_in[2];
    const float* Wh = (const float*)d_in[3];
    const float* bh = (const float*)d_in[4];
    float* out = (float*)d_out;

    cudaFuncSetAttribute(rnn_fused, cudaFuncAttributeMaxDynamicSharedMemorySize, P2_SMEM);

    xsplit_kernel<<<(TT * BB * HH / 4) / 256, 256>>>(x);
    rnn_fused<<<P2_NBLK, 256, P2_SMEM>>>(Wh, Wx, bx, bh, out);
}

// round 11
// speedup vs baseline: 1.1083x; 1.1083x over previous
#include <cuda_runtime.h>
#include <cuda_bf16.h>
#include <cuda_fp16.h>
#include <cstdint>

#define TT 512
#define BB 256
#define HH 1024
#define KK 1024

// ---------------- device globals (static scratch; no allocations) ----------
__device__ __align__(16) unsigned short g_xhi[TT*BB*HH];   // 256MB, fp16(x)
__device__ __align__(16) unsigned short g_hhi[2][BB*HH];
__device__ __align__(16) unsigned short g_hlo[2][BB*HH];
__device__ unsigned g_count4[4 * 32];   // one counter per bt group, 128B apart
__device__ unsigned g_gen4[4 * 32];

// ---------------- helpers ---------------------------------------------------
__device__ __forceinline__ uint32_t smem_u32(const void* p) {
    uint32_t a;
    asm("{ .reg .u64 t; cvta.to.shared.u64 t, %1; cvt.u32.u64 %0, t; }"
        : "=r"(a) : "l"(p));
    return a;
}

__device__ __forceinline__ void ldsm4(uint32_t* r, uint32_t addr) {
    asm volatile("ldmatrix.sync.aligned.m8n8.x4.shared.b16 {%0,%1,%2,%3}, [%4];"
        : "=r"(r[0]), "=r"(r[1]), "=r"(r[2]), "=r"(r[3]) : "r"(addr));
}

// fp16 MMA
__device__ __forceinline__ void mma16816h(float* c, const uint32_t* a, const uint32_t* b) {
    asm volatile("mma.sync.aligned.m16n8k16.row.col.f32.f16.f16.f32 "
        "{%0,%1,%2,%3}, {%4,%5,%6,%7}, {%8,%9}, {%0,%1,%2,%3};"
        : "+f"(c[0]), "+f"(c[1]), "+f"(c[2]), "+f"(c[3])
        : "r"(a[0]), "r"(a[1]), "r"(a[2]), "r"(a[3]), "r"(b[0]), "r"(b[1]));
}

#define CP16(dst, src) \
    asm volatile("{\n\t.reg .u64 g;\n\tcvta.to.global.u64 g, %1;\n\t" \
                 "cp.async.cg.shared.global [%0], [g], 16;\n\t}" \
                 :: "r"(dst), "l"(src) : "memory")
#define CP_COMMIT() asm volatile("cp.async.commit_group;" ::: "memory")
#define CP_WAITN(n) asm volatile("cp.async.wait_group %0;" :: "n"(n) : "memory")

__device__ __forceinline__ float tanh_fast(float x) {
    float e = __expf(2.0f * x);
    return 1.0f - 2.0f / (e + 1.0f);
}

// fp16 split
__device__ __forceinline__ void split2h(float a, float b, uint32_t& hi, uint32_t& lo) {
    __half ha = __float2half_rn(a);
    __half hb = __float2half_rn(b);
    float ra = a - __half2float(ha);
    float rb = b - __half2float(hb);
    __half la = __float2half_rn(ra);
    __half lb = __float2half_rn(rb);
    hi = (uint32_t)__half_as_ushort(ha) | ((uint32_t)__half_as_ushort(hb) << 16);
    lo = (uint32_t)__half_as_ushort(la) | ((uint32_t)__half_as_ushort(lb) << 16);
}

// fp16 pack (hi only)
__device__ __forceinline__ uint32_t pack2h(float a, float b) {
    __half ha = __float2half_rn(a);
    __half hb = __float2half_rn(b);
    return (uint32_t)__half_as_ushort(ha) | ((uint32_t)__half_as_ushort(hb) << 16);
}

// per-bt-group barrier: 32 participating blocks
__device__ __forceinline__ void group_sync(unsigned* cntp, unsigned* genp,
                                           unsigned base, unsigned gen) {
    __syncthreads();
    if (threadIdx.x == 0) {
        const unsigned target = base + gen;
        __threadfence();
        unsigned a = atomicAdd(cntp, 1u);
        if (a == 31u) {
            *(volatile unsigned*)cntp = 0u;
            __threadfence();
            atomicExch(genp, target);
        } else {
            while ((int)(*(volatile unsigned*)genp - target) < 0) __nanosleep(32);
        }
        __threadfence();
    }
    __syncthreads();
}

// ---------------------------------------------------------------------------
// Prep: x (fp32) -> fp16 hi array only (x_lo term dropped this round).
// ---------------------------------------------------------------------------
__global__ void xsplit_kernel(const float* __restrict__ X)
{
    size_t i = (size_t)blockIdx.x * 256 + threadIdx.x;   // float4 index
    float4 v = ((const float4*)X)[i];
    uint2 hi;
    hi.x = pack2h(v.x, v.y);
    hi.y = pack2h(v.z, v.w);
    ((uint2*)g_xhi)[i] = hi;
}

// ---------------------------------------------------------------------------
// Fused persistent RNN: h_t = tanh(x_t@Wx^T + h_{t-1}@Wh^T + bx + bh).
// 128 blocks = 4 bt(64 rows) x 32 jt(32 cols). 256 threads = 8 warps,
// warp tile 16m x 16n, full k=1024 per warp. Wh_hi + Wx_hi resident.
// Per step: 16 chunks of k64, 3-stage cp.async of 3 A streams
// (h_hi, h_lo, x_hi), kk-level fragment double-buffering for ILP.
// Products: h_hi*Wh + h_lo*Wh + x_hi*Wx (6 MMAs per kk per warp).
// ---------------------------------------------------------------------------
#define P2_NBLK 128
#define WH_OFF  0
#define WX_OFF  66048
#define A_OFF   132096            // + stage*24576; streams at +0/8192/16384
#define P2_SMEM 205824

__global__ void __launch_bounds__(256, 1)
rnn_fused(const float* __restrict__ Wh, const float* __restrict__ Wx,
          const float* __restrict__ bx, const float* __restrict__ bh,
          float* __restrict__ out)
{
    extern __shared__ char smem[];
    __shared__ float bsum[32];
    __shared__ unsigned sbase;
    const uint32_t sb = smem_u32(smem);
    const int tid = threadIdx.x;
    const int lane = tid & 31;
    const int w = tid >> 5;
    const int wm = w >> 1;           // 0..3 (16 m rows each)
    const int wn = w & 1;            // 0..1 (16 n cols each)
    const int bidx = blockIdx.x;
    const int jt = bidx & 31, bt = bidx >> 5;
    const int j0 = jt * 32, b0 = bt * 64;

    unsigned* cntp = &g_count4[bt * 32];
    unsigned* genp = &g_gen4[bt * 32];

    float* hfinal = out;
    float* hall = out + (size_t)BB * HH;

    if (tid == 0) sbase = *(volatile unsigned*)genp;
    if (tid < 32) bsum[tid] = bx[j0 + tid] + bh[j0 + tid];

    // resident W tiles (fp16 hi only): 32 j-rows x 1024 k, rows padded 2064B
#pragma unroll 1
    for (int i = tid; i < 32 * 256; i += 256) {
        int row = i >> 8, k4 = i & 255;
        uint32_t off = (uint32_t)(row * 2064 + k4 * 8);
        float4 vh = *(const float4*)(Wh + (size_t)(j0 + row) * KK + k4 * 4);
        uint2 hp;
        hp.x = pack2h(vh.x, vh.y);
        hp.y = pack2h(vh.z, vh.w);
        *(uint2*)(smem + WH_OFF + off) = hp;
        float4 vx = *(const float4*)(Wx + (size_t)(j0 + row) * KK + k4 * 4);
        hp.x = pack2h(vx.x, vx.y);
        hp.y = pack2h(vx.z, vx.w);
        *(uint2*)(smem + WX_OFF + off) = hp;
    }

    // zero this bt group's t=0 hidden-state rows
    {
        uint4 z = make_uint4(0, 0, 0, 0);
        const int sliceBase = b0 * HH / 8;      // uint4 index of row b0
        for (int i = jt * 256 + tid; i < 64 * HH / 8; i += 32 * 256) {
            ((uint4*)g_hhi[0])[sliceBase + i] = z;
            ((uint4*)g_hlo[0])[sliceBase + i] = z;
        }
    }
    __syncthreads();
    const unsigned base = sbase;
    unsigned gen = 1;
    group_sync(cntp, genp, base, gen++);

    // ldmatrix A addressing (swizzled 128B rows)
    const uint32_t aLin = (uint32_t)((wm * 16 + (lane & 15)) * 128 + (lane >> 4) * 16);
    const uint32_t aXor = (uint32_t)((lane & 7) << 4);
    // ldmatrix B addressing (2064B padded rows, resident W)
    const uint32_t bRel = (uint32_t)((wn * 16 + ((lane >> 4) & 1) * 8 + (lane & 7)) * 2064
                                     + ((lane >> 3) & 1) * 16);
    // cp.async coords: rows (tid>>3) and (tid>>3)+32, seg tid&7
    const int cprow = tid >> 3, cpseg = tid & 7;
    const uint32_t aBase = sb + A_OFF;

    // epilogue fragment coordinates
    int erow[2], ecol[2];
#pragma unroll
    for (int p = 0; p < 2; ++p) erow[p] = wm * 16 + (lane >> 2) + p * 8;
#pragma unroll
    for (int ni = 0; ni < 2; ++ni) ecol[ni] = wn * 16 + ni * 8 + (lane & 3) * 2;

#pragma unroll 1
    for (int t = 0; t < TT; ++t) {
        const unsigned short* hrh = g_hhi[t & 1];
        const unsigned short* hrl = g_hlo[t & 1];
        unsigned short* hwh = g_hhi[(t & 1) ^ 1];
        unsigned short* hwl = g_hlo[(t & 1) ^ 1];
        const unsigned short* xh = g_xhi + (size_t)t * (BB * HH);
        float* hat = hall + (size_t)t * (BB * HH);

        float cc[2][4];
#pragma unroll
        for (int b = 0; b < 2; ++b)
#pragma unroll
            for (int q = 0; q < 4; ++q) cc[b][q] = 0.0f;

        // prologue: issue chunks 0 and 1
#pragma unroll
        for (int pc = 0; pc < 2; ++pc) {
            const uint32_t stg = aBase + (uint32_t)(pc * 24576);
#pragma unroll
            for (int j = 0; j < 2; ++j) {
                int row = cprow + 32 * j;
                uint32_t off = (((uint32_t)(row * 128 + cpseg * 16)) ^ ((uint32_t)(row & 7) << 4));
                size_t src = (size_t)(b0 + row) * KK + pc * 64 + cpseg * 8;
                CP16(stg + off,         hrh + src);
                CP16(stg + 8192 + off,  hrl + src);
                CP16(stg + 16384 + off, xh + src);
            }
            CP_COMMIT();
        }

#pragma unroll 1
        for (int c = 0; c < 16; ++c) {
            if (c < 15) { CP_WAITN(1); } else { CP_WAITN(0); }
            __syncthreads();
            if (c + 2 < 16) {
                const uint32_t stg = aBase + (uint32_t)(((c + 2) % 3) * 24576);
#pragma unroll
                for (int j = 0; j < 2; ++j) {
                    int row = cprow + 32 * j;
                    uint32_t off = (((uint32_t)(row * 128 + cpseg * 16)) ^ ((uint32_t)(row & 7) << 4));
                    size_t src = (size_t)(b0 + row) * KK + (c + 2) * 64 + cpseg * 8;
                    CP16(stg + off,         hrh + src);
                    CP16(stg + 8192 + off,  hrl + src);
                    CP16(stg + 16384 + off, xh + src);
                }
                CP_COMMIT();
            }

            const uint32_t stg = aBase + (uint32_t)((c % 3) * 24576);
            const uint32_t kOff = (uint32_t)(c * 128);   // byte offset in W rows

            // kk-level double-buffered fragments: load kk+1 while MMA kk
            uint32_t fah[2][4], fal[2][4], fax[2][4], fbh[2][4], fbx[2][4];
            {
                const uint32_t aoff = aLin ^ aXor;       // kk = 0
                ldsm4(fah[0], stg + aoff);
                ldsm4(fal[0], stg + 8192 + aoff);
                ldsm4(fax[0], stg + 16384 + aoff);
                ldsm4(fbh[0], sb + WH_OFF + bRel + kOff);
                ldsm4(fbx[0], sb + WX_OFF + bRel + kOff);
            }
#pragma unroll
            for (int kk = 0; kk < 4; ++kk) {
                const int cur = kk & 1, nxt = cur ^ 1;
                if (kk < 3) {
                    const uint32_t ka = (kk + 1) * 32;
                    const uint32_t aoff = (aLin + ka) ^ aXor;
                    ldsm4(fah[nxt], stg + aoff);
                    ldsm4(fal[nxt], stg + 8192 + aoff);
                    ldsm4(fax[nxt], stg + 16384 + aoff);
                    ldsm4(fbh[nxt], sb + WH_OFF + bRel + kOff + ka);
                    ldsm4(fbx[nxt], sb + WX_OFF + bRel + kOff + ka);
                }
#pragma unroll
                for (int ni = 0; ni < 2; ++ni) {
                    mma16816h(cc[ni], fax[cur], fbx[cur] + 2 * ni);
                    mma16816h(cc[ni], fah[cur], fbh[cur] + 2 * ni);
                    mma16816h(cc[ni], fal[cur], fbh[cur] + 2 * ni);
                }
            }
        }

        // epilogue: all 256 threads own their 16x16 fragment piece
#pragma unroll
        for (int ni = 0; ni < 2; ++ni)
#pragma unroll
            for (int p = 0; p < 2; ++p) {
                const int col = ecol[ni];
                size_t idx = (size_t)(b0 + erow[p]) * HH + j0 + col;
                float v0 = tanh_fast(cc[ni][2 * p]     + bsum[col]);
                float v1 = tanh_fast(cc[ni][2 * p + 1] + bsum[col + 1]);
                *(float2*)(hat + idx) = make_float2(v0, v1);
                if (t == TT - 1) *(float2*)(hfinal + idx) = make_float2(v0, v1);
                uint32_t hi, lo;
                split2h(v0, v1, hi, lo);
                *(uint32_t*)(hwh + idx) = hi;
                *(uint32_t*)(hwl + idx) = lo;
            }

        group_sync(cntp, genp, base, gen++);
    }
}

// ---------------------------------------------------------------------------
extern "C" void kernel_launch(void* const* d_in, const int* in_sizes, int n_in,
                              void* d_out, int out_size)
{
    (void)in_sizes; (void)n_in; (void)out_size;
    const float* x  = (const float*)d_in[0];
    const float* Wx = (const float*)d_in[1];
    const float* bx = (const float*)d_in[2];
    const float* Wh = (const float*)d_in[3];
    const float* bh = (const float*)d_in[4];
    float* out = (float*)d_out;

    cudaFuncSetAttribute(rnn_fused, cudaFuncAttributeMaxDynamicSharedMemorySize, P2_SMEM);

    xsplit_kernel<<<(TT * BB * HH / 4) / 256, 256>>>(x);
    rnn_fused<<<P2_NBLK, 256, P2_SMEM>>>(Wh, Wx, bx, bh, out);
}

// round 12
// speedup vs baseline: 1.5191x; 1.3706x over previous
#include <cuda_runtime.h>
#include <cuda_bf16.h>
#include <cuda_fp16.h>
#include <cstdint>

#define TT 512
#define BB 256
#define HH 1024
#define KK 1024

// ---------------- device globals (static scratch; no allocations) ----------
__device__ __align__(16) unsigned short g_hhi[2][BB*HH];
__device__ __align__(16) unsigned short g_hlo[2][BB*HH];
__device__ unsigned g_count8[8 * 32];   // one counter per bt group, 128B apart
__device__ unsigned g_gen8[8 * 32];

// ---------------- helpers ---------------------------------------------------
__device__ __forceinline__ uint32_t smem_u32(const void* p) {
    uint32_t a;
    asm("{ .reg .u64 t; cvta.to.shared.u64 t, %1; cvt.u32.u64 %0, t; }"
        : "=r"(a) : "l"(p));
    return a;
}

__device__ __forceinline__ void ldsm4(uint32_t* r, uint32_t addr) {
    asm volatile("ldmatrix.sync.aligned.m8n8.x4.shared.b16 {%0,%1,%2,%3}, [%4];"
        : "=r"(r[0]), "=r"(r[1]), "=r"(r[2]), "=r"(r[3]) : "r"(addr));
}

// fp16 MMA
__device__ __forceinline__ void mma16816h(float* c, const uint32_t* a, const uint32_t* b) {
    asm volatile("mma.sync.aligned.m16n8k16.row.col.f32.f16.f16.f32 "
        "{%0,%1,%2,%3}, {%4,%5,%6,%7}, {%8,%9}, {%0,%1,%2,%3};"
        : "+f"(c[0]), "+f"(c[1]), "+f"(c[2]), "+f"(c[3])
        : "r"(a[0]), "r"(a[1]), "r"(a[2]), "r"(a[3]), "r"(b[0]), "r"(b[1]));
}

#define CP16(dst, src) \
    asm volatile("{\n\t.reg .u64 g;\n\tcvta.to.global.u64 g, %1;\n\t" \
                 "cp.async.cg.shared.global [%0], [g], 16;\n\t}" \
                 :: "r"(dst), "l"(src) : "memory")
#define CP_COMMIT() asm volatile("cp.async.commit_group;" ::: "memory")
#define CP_WAITN(n) asm volatile("cp.async.wait_group %0;" :: "n"(n) : "memory")

#define GROUP_BAR(id) asm volatile("bar.sync %0, %1;" :: "r"(id), "r"(128) : "memory")

__device__ __forceinline__ float tanh_fast(float x) {
    float e = __expf(2.0f * x);
    return 1.0f - 2.0f / (e + 1.0f);
}

// fp16 split
__device__ __forceinline__ void split2h(float a, float b, uint32_t& hi, uint32_t& lo) {
    __half ha = __float2half_rn(a);
    __half hb = __float2half_rn(b);
    float ra = a - __half2float(ha);
    float rb = b - __half2float(hb);
    __half la = __float2half_rn(ra);
    __half lb = __float2half_rn(rb);
    hi = (uint32_t)__half_as_ushort(ha) | ((uint32_t)__half_as_ushort(hb) << 16);
    lo = (uint32_t)__half_as_ushort(la) | ((uint32_t)__half_as_ushort(lb) << 16);
}

// fp16 pack (hi only)
__device__ __forceinline__ uint32_t pack2h(float a, float b) {
    __half ha = __float2half_rn(a);
    __half hb = __float2half_rn(b);
    return (uint32_t)__half_as_ushort(ha) | ((uint32_t)__half_as_ushort(hb) << 16);
}

// per-bt-group barrier: 16 participating blocks
__device__ __forceinline__ void group_sync(unsigned* cntp, unsigned* genp,
                                           unsigned base, unsigned gen) {
    __syncthreads();
    if (threadIdx.x == 0) {
        const unsigned target = base + gen;
        __threadfence();
        unsigned a = atomicAdd(cntp, 1u);
        if (a == 15u) {
            *(volatile unsigned*)cntp = 0u;
            __threadfence();
            atomicExch(genp, target);
        } else {
            while ((int)(*(volatile unsigned*)genp - target) < 0) __nanosleep(32);
        }
        __threadfence();
    }
    __syncthreads();
}

// ---------------------------------------------------------------------------
// Phase 1: XP = x @ Wx^T + bx, 1-term fp16 (xh @ Wxh). Numerics calibrated by
// R11 (same x schedule, measured 3.04e-4 combined).
// Block 128m x 128n, 8 warps (64m x 32n), k-chunk 32, reg-staged.
// ---------------------------------------------------------------------------
#define P1_AH 0
#define P1_BH 10240
#define P1_SMEM 20480

__global__ void __launch_bounds__(256, 1)
xproj_hmma(const float* __restrict__ X, const float* __restrict__ Wx,
           const float* __restrict__ bx, float* __restrict__ XP)
{
    extern __shared__ char smem[];
    __shared__ float bxs[128];
    const uint32_t sb = smem_u32(smem);
    const int tid = threadIdx.x;
    const int lane = tid & 31;
    const int w = tid >> 5;
    const int wm = w >> 2;
    const int wn = w & 3;
    const int n0 = blockIdx.x * 128;
    const int m0 = blockIdx.y * 128;

    if (tid < 128) bxs[tid] = bx[n0 + tid];

    const uint32_t aRel = (uint32_t)((wm * 64 + (lane & 15)) * 80 + (lane >> 4) * 16);
    const uint32_t bRel = (uint32_t)((wn * 32 + ((lane >> 4) & 1) * 8 + (lane & 7)) * 80
                                     + ((lane >> 3) & 1) * 16);

    float cc[4][4][4];
#pragma unroll
    for (int a = 0; a < 4; ++a)
#pragma unroll
        for (int b = 0; b < 4; ++b)
#pragma unroll
            for (int q = 0; q < 4; ++q) cc[a][b][q] = 0.0f;

    float4 va[4], vb[4];
#pragma unroll
    for (int i = 0; i < 4; ++i) {
        int u = tid + 256 * i;
        int row = u >> 3, k4 = u & 7;
        va[i] = *(const float4*)(X + (size_t)(m0 + row) * KK + k4 * 4);
        vb[i] = *(const float4*)(Wx + (size_t)(n0 + row) * KK + k4 * 4);
    }

#pragma unroll 1
    for (int c = 0; c < 32; ++c) {
#pragma unroll
        for (int i = 0; i < 4; ++i) {
            int u = tid + 256 * i;
            int row = u >> 3, k4 = u & 7;
            uint32_t off = (uint32_t)(row * 80 + k4 * 8);
            uint2 hp;
            hp.x = pack2h(va[i].x, va[i].y);
            hp.y = pack2h(va[i].z, va[i].w);
            *(uint2*)(smem + P1_AH + off) = hp;
            hp.x = pack2h(vb[i].x, vb[i].y);
            hp.y = pack2h(vb[i].z, vb[i].w);
            *(uint2*)(smem + P1_BH + off) = hp;
        }
        __syncthreads();

        if (c < 31) {
            const int k0 = (c + 1) * 32;
#pragma unroll
            for (int i = 0; i < 4; ++i) {
                int u = tid + 256 * i;
                int row = u >> 3, k4 = u & 7;
                va[i] = *(const float4*)(X + (size_t)(m0 + row) * KK + k0 + k4 * 4);
                vb[i] = *(const float4*)(Wx + (size_t)(n0 + row) * KK + k0 + k4 * 4);
            }
        }

#pragma unroll
        for (int kk = 0; kk < 2; ++kk) {
            const uint32_t ka = kk * 32;
            uint32_t ah[4][4], bh[8];
#pragma unroll
            for (int mi = 0; mi < 4; ++mi)
                ldsm4(ah[mi], sb + P1_AH + aRel + mi * 1280 + ka);
            ldsm4(bh,     sb + P1_BH + bRel + ka);
            ldsm4(bh + 4, sb + P1_BH + bRel + 1280 + ka);
#pragma unroll
            for (int mi = 0; mi < 4; ++mi)
#pragma unroll
                for (int ni = 0; ni < 4; ++ni)
                    mma16816h(cc[mi][ni], ah[mi], bh + 2 * ni);
        }
        __syncthreads();
    }

#pragma unroll
    for (int mi = 0; mi < 4; ++mi)
#pragma unroll
        for (int ni = 0; ni < 4; ++ni)
#pragma unroll
            for (int p = 0; p < 2; ++p) {
                int row = wm * 64 + mi * 16 + (lane >> 2) + p * 8;
                int col = wn * 32 + ni * 8 + (lane & 3) * 2;
                float2 v;
                v.x = cc[mi][ni][2 * p]     + bxs[col];
                v.y = cc[mi][ni][2 * p + 1] + bxs[col + 1];
                *(float2*)(XP + (size_t)(m0 + row) * HH + n0 + col) = v;
            }
}

// ---------------------------------------------------------------------------
// Phase 2: persistent RNN, retiled 32m x 64n. 128 blocks = 8 bt x 16 jt.
// 256 threads = 2 kg x (2 wm x 2 wn), warp tile 16m x 32n, k half per kg.
// Wh_hi resident (64 rows x 2064B = 132KB). h streamed hi/lo via cp.async,
// 3-stage. fp16 2-term h product. Partial exchange padded stride 66.
// ---------------------------------------------------------------------------
#define P2_NBLK 128
#define WH_OFF  0
#define A_OFF   132096            // + kg*24576 + stage*8192 (+4096 for lo)
#define PSM_OFF 181248            // 32 x 66 floats = 8448B
#define P2_SMEM 189696

__global__ void __launch_bounds__(256, 1)
rnn_hmma(const float* __restrict__ Wh, const float* __restrict__ bh,
         float* __restrict__ out)
{
    extern __shared__ char smem[];
    __shared__ float bhs[64];
    __shared__ unsigned sbase;
    const uint32_t sb = smem_u32(smem);
    const int tid = threadIdx.x;
    const int lane = tid & 31;
    const int w = tid >> 5;
    const int kg = w >> 2;           // k half
    const int wl = w & 3;
    const int wm = wl >> 1;          // 0..1 (16 m rows)
    const int wn = wl & 1;           // 0..1 (32 n cols)
    const int tig = tid & 127;
    const int bidx = blockIdx.x;
    const int jt = bidx & 15, bt = bidx >> 4;
    const int j0 = jt * 64, b0 = bt * 32;

    unsigned* cntp = &g_count8[bt * 32];
    unsigned* genp = &g_gen8[bt * 32];

    float* hfinal = out;
    float* hall = out + (size_t)BB * HH;
    float* psm = (float*)(smem + PSM_OFF);

    if (tid == 0) sbase = *(volatile unsigned*)genp;
    if (tid < 64) bhs[tid] = bh[j0 + tid];

    // resident Wh tile (fp16 hi): 64 j-rows x 1024 k, rows padded 2064B
#pragma unroll 1
    for (int i = tid; i < 64 * 256; i += 256) {
        int row = i >> 8, k4 = i & 255;
        float4 v = *(const float4*)(Wh + (size_t)(j0 + row) * KK + k4 * 4);
        uint2 hp;
        hp.x = pack2h(v.x, v.y);
        hp.y = pack2h(v.z, v.w);
        *(uint2*)(smem + WH_OFF + (uint32_t)(row * 2064 + k4 * 8)) = hp;
    }

    // zero this bt group's t=0 hidden-state rows (16 blocks share 32 rows)
    {
        uint4 z = make_uint4(0, 0, 0, 0);
        const int sliceBase = b0 * HH / 8;      // uint4 index of row b0
        int i = jt * 256 + tid;                 // 0..4095 exactly covers slice
        ((uint4*)g_hhi[0])[sliceBase + i] = z;
        ((uint4*)g_hlo[0])[sliceBase + i] = z;
    }
    __syncthreads();
    const unsigned base = sbase;
    unsigned gen = 1;
    group_sync(cntp, genp, base, gen++);

    // ldmatrix A addressing (swizzled 128B rows, 32-row buffer)
    const uint32_t aLin = (uint32_t)((wm * 16 + (lane & 15)) * 128 + (lane >> 4) * 16);
    const uint32_t aXor = (uint32_t)((lane & 7) << 4);
    // ldmatrix B addressing (2064B padded rows); frag f adds f*16*2064
    const uint32_t bRel = (uint32_t)((wn * 32 + ((lane >> 4) & 1) * 8 + (lane & 7)) * 2064
                                     + ((lane >> 3) & 1) * 16);
    const uint32_t kgOff = (uint32_t)(kg * 1024);   // byte offset into Wh rows
    // cp.async coords: rows cprow, cprow+16; seg cpseg
    const int cprow = tig >> 3, cpseg = tig & 7;
    const uint32_t aBase = sb + A_OFF + (uint32_t)(kg * 24576);
    const size_t kSrc0 = (size_t)kg * 512 + cpseg * 8;

    // epilogue fragment coordinates (local within 32x64 tile)
    int erow[2], ecol[2][2];
#pragma unroll
    for (int p = 0; p < 2; ++p) erow[p] = wm * 16 + (lane >> 2) + p * 8;
#pragma unroll
    for (int f = 0; f < 2; ++f)
#pragma unroll
        for (int ni = 0; ni < 2; ++ni)
            ecol[f][ni] = wn * 32 + f * 16 + ni * 8 + (lane & 3) * 2;

#pragma unroll 1
    for (int t = 0; t < TT; ++t) {
        const unsigned short* hrh = g_hhi[t & 1];
        const unsigned short* hrl = g_hlo[t & 1];
        unsigned short* hwh = g_hhi[(t & 1) ^ 1];
        unsigned short* hwl = g_hlo[(t & 1) ^ 1];
        float* hat = hall + (size_t)t * (BB * HH);

        // xp prefetch (kg0 only; consumed in epilogue)
        float2 xpv[2][2][2];
        if (kg == 0) {
#pragma unroll
            for (int f = 0; f < 2; ++f)
#pragma unroll
                for (int ni = 0; ni < 2; ++ni)
#pragma unroll
                    for (int p = 0; p < 2; ++p)
                        xpv[f][ni][p] = *(const float2*)(hat +
                            (size_t)(b0 + erow[p]) * HH + j0 + ecol[f][ni]);
        }

        float cc[2][2][4];
#pragma unroll
        for (int a = 0; a < 2; ++a)
#pragma unroll
            for (int b = 0; b < 2; ++b)
#pragma unroll
                for (int q = 0; q < 4; ++q) cc[a][b][q] = 0.0f;

        // prologue: issue chunks 0 and 1
#pragma unroll
        for (int pc = 0; pc < 2; ++pc) {
            const uint32_t stg = aBase + (uint32_t)(pc * 8192);
#pragma unroll
            for (int j = 0; j < 2; ++j) {
                int row = cprow + 16 * j;
                uint32_t off = (((uint32_t)(row * 128 + cpseg * 16)) ^ ((uint32_t)(row & 7) << 4));
                size_t src = (size_t)(b0 + row) * KK + kSrc0 + pc * 64;
                CP16(stg + off,        hrh + src);
                CP16(stg + 4096 + off, hrl + src);
            }
            CP_COMMIT();
        }

#pragma unroll 1
        for (int c = 0; c < 8; ++c) {
            if (c < 7) { CP_WAITN(1); } else { CP_WAITN(0); }
            GROUP_BAR(kg + 1);
            if (c + 2 < 8) {
                const uint32_t stg = aBase + (uint32_t)(((c + 2) % 3) * 8192);
#pragma unroll
                for (int j = 0; j < 2; ++j) {
                    int row = cprow + 16 * j;
                    uint32_t off = (((uint32_t)(row * 128 + cpseg * 16)) ^ ((uint32_t)(row & 7) << 4));
                    size_t src = (size_t)(b0 + row) * KK + kSrc0 + (c + 2) * 64;
                    CP16(stg + off,        hrh + src);
                    CP16(stg + 4096 + off, hrl + src);
                }
                CP_COMMIT();
            }

            const uint32_t stg = aBase + (uint32_t)((c % 3) * 8192);
            const uint32_t kOffB = kgOff + (uint32_t)(c * 128);
#pragma unroll
            for (int kk = 0; kk < 4; ++kk) {
                const uint32_t ka = kk * 32;
                const uint32_t aoff = (aLin + ka) ^ aXor;
                uint32_t ah[4], al[4], bf0[4], bf1[4];
                ldsm4(ah, stg + aoff);
                ldsm4(al, stg + 4096 + aoff);
                ldsm4(bf0, sb + WH_OFF + bRel + kOffB + ka);
                ldsm4(bf1, sb + WH_OFF + bRel + 33024 + kOffB + ka);
#pragma unroll
                for (int ni = 0; ni < 2; ++ni) {
                    mma16816h(cc[0][ni], ah, bf0 + 2 * ni);
                    mma16816h(cc[0][ni], al, bf0 + 2 * ni);
                    mma16816h(cc[1][ni], ah, bf1 + 2 * ni);
                    mma16816h(cc[1][ni], al, bf1 + 2 * ni);
                }
            }
        }

        // kg1 publishes partials (stride 66 to avoid bank conflicts)
        if (kg == 1) {
#pragma unroll
            for (int f = 0; f < 2; ++f)
#pragma unroll
                for (int ni = 0; ni < 2; ++ni)
#pragma unroll
                    for (int p = 0; p < 2; ++p)
                        *(float2*)&psm[erow[p] * 66 + ecol[f][ni]] =
                            make_float2(cc[f][ni][2 * p], cc[f][ni][2 * p + 1]);
        }
        __syncthreads();

        // kg0 combines + epilogue
        if (kg == 0) {
#pragma unroll
            for (int f = 0; f < 2; ++f)
#pragma unroll
                for (int ni = 0; ni < 2; ++ni)
#pragma unroll
                    for (int p = 0; p < 2; ++p) {
                        const int row = erow[p], col = ecol[f][ni];
                        float2 pp = *(float2*)&psm[row * 66 + col];
                        size_t idx = (size_t)(b0 + row) * HH + j0 + col;
                        float v0 = tanh_fast(cc[f][ni][2 * p]     + pp.x + bhs[col]     + xpv[f][ni][p].x);
                        float v1 = tanh_fast(cc[f][ni][2 * p + 1] + pp.y + bhs[col + 1] + xpv[f][ni][p].y);
                        *(float2*)(hat + idx) = make_float2(v0, v1);
                        if (t == TT - 1) *(float2*)(hfinal + idx) = make_float2(v0, v1);
                        uint32_t hi, lo;
                        split2h(v0, v1, hi, lo);
                        *(uint32_t*)(hwh + idx) = hi;
                        *(uint32_t*)(hwl + idx) = lo;
                    }
        }

        group_sync(cntp, genp, base, gen++);
    }
}

// ---------------------------------------------------------------------------
extern "C" void kernel_launch(void* const* d_in, const int* in_sizes, int n_in,
                              void* d_out, int out_size)
{
    (void)in_sizes; (void)n_in; (void)out_size;
    const float* x  = (const float*)d_in[0];
    const float* Wx = (const float*)d_in[1];
    const float* bx = (const float*)d_in[2];
    const float* Wh = (const float*)d_in[3];
    const float* bh = (const float*)d_in[4];
    float* out = (float*)d_out;
    float* xp = out + (size_t)BB * HH;   // h_all region doubles as xp scratch

    cudaFuncSetAttribute(xproj_hmma, cudaFuncAttributeMaxDynamicSharedMemorySize, P1_SMEM);
    cudaFuncSetAttribute(rnn_hmma,  cudaFuncAttributeMaxDynamicSharedMemorySize, P2_SMEM);

    dim3 g1(HH / 128, (TT * BB) / 128);
    xproj_hmma<<<g1, 256, P1_SMEM>>>(x, Wx, bx, xp);
    rnn_hmma<<<P2_NBLK, 256, P2_SMEM>>>(Wh, bh, out);
}

// round 13
// speedup vs baseline: 1.7082x; 1.1245x over previous
#include <cuda_runtime.h>
#include <cuda_bf16.h>
#include <cuda_fp16.h>
#include <cstdint>

#define TT 512
#define BB 256
#define HH 1024
#define KK 1024

// ---------------- device globals (static scratch; no allocations) ----------
__device__ __align__(16) unsigned short g_hhi[2][BB*HH];
__device__ unsigned g_count8[8 * 32];   // one counter per bt group, 128B apart
__device__ unsigned g_gen8[8 * 32];

// ---------------- helpers ---------------------------------------------------
__device__ __forceinline__ uint32_t smem_u32(const void* p) {
    uint32_t a;
    asm("{ .reg .u64 t; cvta.to.shared.u64 t, %1; cvt.u32.u64 %0, t; }"
        : "=r"(a) : "l"(p));
    return a;
}

__device__ __forceinline__ void ldsm4(uint32_t* r, uint32_t addr) {
    asm volatile("ldmatrix.sync.aligned.m8n8.x4.shared.b16 {%0,%1,%2,%3}, [%4];"
        : "=r"(r[0]), "=r"(r[1]), "=r"(r[2]), "=r"(r[3]) : "r"(addr));
}

// fp16 MMA
__device__ __forceinline__ void mma16816h(float* c, const uint32_t* a, const uint32_t* b) {
    asm volatile("mma.sync.aligned.m16n8k16.row.col.f32.f16.f16.f32 "
        "{%0,%1,%2,%3}, {%4,%5,%6,%7}, {%8,%9}, {%0,%1,%2,%3};"
        : "+f"(c[0]), "+f"(c[1]), "+f"(c[2]), "+f"(c[3])
        : "r"(a[0]), "r"(a[1]), "r"(a[2]), "r"(a[3]), "r"(b[0]), "r"(b[1]));
}

#define CP16(dst, src) \
    asm volatile("{\n\t.reg .u64 g;\n\tcvta.to.global.u64 g, %1;\n\t" \
                 "cp.async.cg.shared.global [%0], [g], 16;\n\t}" \
                 :: "r"(dst), "l"(src) : "memory")
#define CP_COMMIT() asm volatile("cp.async.commit_group;" ::: "memory")
#define CP_WAITN(n) asm volatile("cp.async.wait_group %0;" :: "n"(n) : "memory")

#define GROUP_BAR(id) asm volatile("bar.sync %0, %1;" :: "r"(id), "r"(128) : "memory")

__device__ __forceinline__ float tanh_fast(float x) {
    float e = __expf(2.0f * x);
    return 1.0f - 2.0f / (e + 1.0f);
}

// fp16 pack
__device__ __forceinline__ uint32_t pack2h(float a, float b) {
    __half ha = __float2half_rn(a);
    __half hb = __float2half_rn(b);
    return (uint32_t)__half_as_ushort(ha) | ((uint32_t)__half_as_ushort(hb) << 16);
}

// per-bt-group barrier: 16 participating blocks
__device__ __forceinline__ void group_sync(unsigned* cntp, unsigned* genp,
                                           unsigned base, unsigned gen) {
    __syncthreads();
    if (threadIdx.x == 0) {
        const unsigned target = base + gen;
        __threadfence();
        unsigned a = atomicAdd(cntp, 1u);
        if (a == 15u) {
            *(volatile unsigned*)cntp = 0u;
            __threadfence();
            atomicExch(genp, target);
        } else {
            while ((int)(*(volatile unsigned*)genp - target) < 0) __nanosleep(32);
        }
        __threadfence();
    }
    __syncthreads();
}

// ---------------------------------------------------------------------------
// Phase 1 (UNCHANGED from R12): XP = x @ Wx^T + bx, 1-term fp16.
// ---------------------------------------------------------------------------
#define P1_AH 0
#define P1_BH 10240
#define P1_SMEM 20480

__global__ void __launch_bounds__(256, 1)
xproj_hmma(const float* __restrict__ X, const float* __restrict__ Wx,
           const float* __restrict__ bx, float* __restrict__ XP)
{
    extern __shared__ char smem[];
    __shared__ float bxs[128];
    const uint32_t sb = smem_u32(smem);
    const int tid = threadIdx.x;
    const int lane = tid & 31;
    const int w = tid >> 5;
    const int wm = w >> 2;
    const int wn = w & 3;
    const int n0 = blockIdx.x * 128;
    const int m0 = blockIdx.y * 128;

    if (tid < 128) bxs[tid] = bx[n0 + tid];

    const uint32_t aRel = (uint32_t)((wm * 64 + (lane & 15)) * 80 + (lane >> 4) * 16);
    const uint32_t bRel = (uint32_t)((wn * 32 + ((lane >> 4) & 1) * 8 + (lane & 7)) * 80
                                     + ((lane >> 3) & 1) * 16);

    float cc[4][4][4];
#pragma unroll
    for (int a = 0; a < 4; ++a)
#pragma unroll
        for (int b = 0; b < 4; ++b)
#pragma unroll
            for (int q = 0; q < 4; ++q) cc[a][b][q] = 0.0f;

    float4 va[4], vb[4];
#pragma unroll
    for (int i = 0; i < 4; ++i) {
        int u = tid + 256 * i;
        int row = u >> 3, k4 = u & 7;
        va[i] = *(const float4*)(X + (size_t)(m0 + row) * KK + k4 * 4);
        vb[i] = *(const float4*)(Wx + (size_t)(n0 + row) * KK + k4 * 4);
    }

#pragma unroll 1
    for (int c = 0; c < 32; ++c) {
#pragma unroll
        for (int i = 0; i < 4; ++i) {
            int u = tid + 256 * i;
            int row = u >> 3, k4 = u & 7;
            uint32_t off = (uint32_t)(row * 80 + k4 * 8);
            uint2 hp;
            hp.x = pack2h(va[i].x, va[i].y);
            hp.y = pack2h(va[i].z, va[i].w);
            *(uint2*)(smem + P1_AH + off) = hp;
            hp.x = pack2h(vb[i].x, vb[i].y);
            hp.y = pack2h(vb[i].z, vb[i].w);
            *(uint2*)(smem + P1_BH + off) = hp;
        }
        __syncthreads();

        if (c < 31) {
            const int k0 = (c + 1) * 32;
#pragma unroll
            for (int i = 0; i < 4; ++i) {
                int u = tid + 256 * i;
                int row = u >> 3, k4 = u & 7;
                va[i] = *(const float4*)(X + (size_t)(m0 + row) * KK + k0 + k4 * 4);
                vb[i] = *(const float4*)(Wx + (size_t)(n0 + row) * KK + k0 + k4 * 4);
            }
        }

#pragma unroll
        for (int kk = 0; kk < 2; ++kk) {
            const uint32_t ka = kk * 32;
            uint32_t ah[4][4], bh[8];
#pragma unroll
            for (int mi = 0; mi < 4; ++mi)
                ldsm4(ah[mi], sb + P1_AH + aRel + mi * 1280 + ka);
            ldsm4(bh,     sb + P1_BH + bRel + ka);
            ldsm4(bh + 4, sb + P1_BH + bRel + 1280 + ka);
#pragma unroll
            for (int mi = 0; mi < 4; ++mi)
#pragma unroll
                for (int ni = 0; ni < 4; ++ni)
                    mma16816h(cc[mi][ni], ah[mi], bh + 2 * ni);
        }
        __syncthreads();
    }

#pragma unroll
    for (int mi = 0; mi < 4; ++mi)
#pragma unroll
        for (int ni = 0; ni < 4; ++ni)
#pragma unroll
            for (int p = 0; p < 2; ++p) {
                int row = wm * 64 + mi * 16 + (lane >> 2) + p * 8;
                int col = wn * 32 + ni * 8 + (lane & 3) * 2;
                float2 v;
                v.x = cc[mi][ni][2 * p]     + bxs[col];
                v.y = cc[mi][ni][2 * p + 1] + bxs[col + 1];
                *(float2*)(XP + (size_t)(m0 + row) * HH + n0 + col) = v;
            }
}

// ---------------------------------------------------------------------------
// Phase 2 v6: 1-term h product (h_hi @ Wh_hi). Structure = R12 retile
// (32m x 64n, 8 bt x 16 jt, 2 kg x 4 warps), minus the h_lo stream.
// ---------------------------------------------------------------------------
#define P2_NBLK 128
#define WH_OFF  0
#define A_OFF   132096            // + kg*12288 + stage*4096
#define PSM_OFF 156672            // 32 x 66 floats = 8448B
#define P2_SMEM 165120

__global__ void __launch_bounds__(256, 1)
rnn_hmma(const float* __restrict__ Wh, const float* __restrict__ bh,
         float* __restrict__ out)
{
    extern __shared__ char smem[];
    __shared__ float bhs[64];
    __shared__ unsigned sbase;
    const uint32_t sb = smem_u32(smem);
    const int tid = threadIdx.x;
    const int lane = tid & 31;
    const int w = tid >> 5;
    const int kg = w >> 2;           // k half
    const int wl = w & 3;
    const int wm = wl >> 1;          // 0..1 (16 m rows)
    const int wn = wl & 1;           // 0..1 (32 n cols)
    const int tig = tid & 127;
    const int bidx = blockIdx.x;
    const int jt = bidx & 15, bt = bidx >> 4;
    const int j0 = jt * 64, b0 = bt * 32;

    unsigned* cntp = &g_count8[bt * 32];
    unsigned* genp = &g_gen8[bt * 32];

    float* hfinal = out;
    float* hall = out + (size_t)BB * HH;
    float* psm = (float*)(smem + PSM_OFF);

    if (tid == 0) sbase = *(volatile unsigned*)genp;
    if (tid < 64) bhs[tid] = bh[j0 + tid];

    // resident Wh tile (fp16 hi): 64 j-rows x 1024 k, rows padded 2064B
#pragma unroll 1
    for (int i = tid; i < 64 * 256; i += 256) {
        int row = i >> 8, k4 = i & 255;
        float4 v = *(const float4*)(Wh + (size_t)(j0 + row) * KK + k4 * 4);
        uint2 hp;
        hp.x = pack2h(v.x, v.y);
        hp.y = pack2h(v.z, v.w);
        *(uint2*)(smem + WH_OFF + (uint32_t)(row * 2064 + k4 * 8)) = hp;
    }

    // zero this bt group's t=0 hidden-state rows (16 blocks share 32 rows)
    {
        uint4 z = make_uint4(0, 0, 0, 0);
        const int sliceBase = b0 * HH / 8;      // uint4 index of row b0
        int i = jt * 256 + tid;                 // 0..4095 exactly covers slice
        ((uint4*)g_hhi[0])[sliceBase + i] = z;
    }
    __syncthreads();
    const unsigned base = sbase;
    unsigned gen = 1;
    group_sync(cntp, genp, base, gen++);

    // ldmatrix A addressing (swizzled 128B rows, 32-row buffer)
    const uint32_t aLin = (uint32_t)((wm * 16 + (lane & 15)) * 128 + (lane >> 4) * 16);
    const uint32_t aXor = (uint32_t)((lane & 7) << 4);
    // ldmatrix B addressing (2064B padded rows); frag f adds f*16*2064
    const uint32_t bRel = (uint32_t)((wn * 32 + ((lane >> 4) & 1) * 8 + (lane & 7)) * 2064
                                     + ((lane >> 3) & 1) * 16);
    const uint32_t kgOff = (uint32_t)(kg * 1024);   // byte offset into Wh rows
    // cp.async coords: rows cprow, cprow+16; seg cpseg
    const int cprow = tig >> 3, cpseg = tig & 7;
    const uint32_t aBase = sb + A_OFF + (uint32_t)(kg * 12288);
    const size_t kSrc0 = (size_t)kg * 512 + cpseg * 8;

    // epilogue fragment coordinates (local within 32x64 tile)
    int erow[2], ecol[2][2];
#pragma unroll
    for (int p = 0; p < 2; ++p) erow[p] = wm * 16 + (lane >> 2) + p * 8;
#pragma unroll
    for (int f = 0; f < 2; ++f)
#pragma unroll
        for (int ni = 0; ni < 2; ++ni)
            ecol[f][ni] = wn * 32 + f * 16 + ni * 8 + (lane & 3) * 2;

#pragma unroll 1
    for (int t = 0; t < TT; ++t) {
        const unsigned short* hrh = g_hhi[t & 1];
        unsigned short* hwh = g_hhi[(t & 1) ^ 1];
        float* hat = hall + (size_t)t * (BB * HH);

        // xp prefetch (kg0 only; consumed in epilogue)
        float2 xpv[2][2][2];
        if (kg == 0) {
#pragma unroll
            for (int f = 0; f < 2; ++f)
#pragma unroll
                for (int ni = 0; ni < 2; ++ni)
#pragma unroll
                    for (int p = 0; p < 2; ++p)
                        xpv[f][ni][p] = *(const float2*)(hat +
                            (size_t)(b0 + erow[p]) * HH + j0 + ecol[f][ni]);
        }

        float cc[2][2][4];
#pragma unroll
        for (int a = 0; a < 2; ++a)
#pragma unroll
            for (int b = 0; b < 2; ++b)
#pragma unroll
                for (int q = 0; q < 4; ++q) cc[a][b][q] = 0.0f;

        // prologue: issue chunks 0 and 1
#pragma unroll
        for (int pc = 0; pc < 2; ++pc) {
            const uint32_t stg = aBase + (uint32_t)(pc * 4096);
#pragma unroll
            for (int j = 0; j < 2; ++j) {
                int row = cprow + 16 * j;
                uint32_t off = (((uint32_t)(row * 128 + cpseg * 16)) ^ ((uint32_t)(row & 7) << 4));
                CP16(stg + off, hrh + (size_t)(b0 + row) * KK + kSrc0 + pc * 64);
            }
            CP_COMMIT();
        }

#pragma unroll 1
        for (int c = 0; c < 8; ++c) {
            if (c < 7) { CP_WAITN(1); } else { CP_WAITN(0); }
            GROUP_BAR(kg + 1);
            if (c + 2 < 8) {
                const uint32_t stg = aBase + (uint32_t)(((c + 2) % 3) * 4096);
#pragma unroll
                for (int j = 0; j < 2; ++j) {
                    int row = cprow + 16 * j;
                    uint32_t off = (((uint32_t)(row * 128 + cpseg * 16)) ^ ((uint32_t)(row & 7) << 4));
                    CP16(stg + off, hrh + (size_t)(b0 + row) * KK + kSrc0 + (c + 2) * 64);
                }
                CP_COMMIT();
            }

            const uint32_t stg = aBase + (uint32_t)((c % 3) * 4096);
            const uint32_t kOffB = kgOff + (uint32_t)(c * 128);
#pragma unroll
            for (int kk = 0; kk < 4; ++kk) {
                const uint32_t ka = kk * 32;
                const uint32_t aoff = (aLin + ka) ^ aXor;
                uint32_t ah[4], bf0[4], bf1[4];
                ldsm4(ah, stg + aoff);
                ldsm4(bf0, sb + WH_OFF + bRel + kOffB + ka);
                ldsm4(bf1, sb + WH_OFF + bRel + 33024 + kOffB + ka);
#pragma unroll
                for (int ni = 0; ni < 2; ++ni) {
                    mma16816h(cc[0][ni], ah, bf0 + 2 * ni);
                    mma16816h(cc[1][ni], ah, bf1 + 2 * ni);
                }
            }
        }

        // kg1 publishes partials (stride 66 to avoid bank conflicts)
        if (kg == 1) {
#pragma unroll
            for (int f = 0; f < 2; ++f)
#pragma unroll
                for (int ni = 0; ni < 2; ++ni)
#pragma unroll
                    for (int p = 0; p < 2; ++p)
                        *(float2*)&psm[erow[p] * 66 + ecol[f][ni]] =
                            make_float2(cc[f][ni][2 * p], cc[f][ni][2 * p + 1]);
        }
        __syncthreads();

        // kg0 combines + epilogue
        if (kg == 0) {
#pragma unroll
            for (int f = 0; f < 2; ++f)
#pragma unroll
                for (int ni = 0; ni < 2; ++ni)
#pragma unroll
                    for (int p = 0; p < 2; ++p) {
                        const int row = erow[p], col = ecol[f][ni];
                        float2 pp = *(float2*)&psm[row * 66 + col];
                        size_t idx = (size_t)(b0 + row) * HH + j0 + col;
                        float v0 = tanh_fast(cc[f][ni][2 * p]     + pp.x + bhs[col]     + xpv[f][ni][p].x);
                        float v1 = tanh_fast(cc[f][ni][2 * p + 1] + pp.y + bhs[col + 1] + xpv[f][ni][p].y);
                        *(float2*)(hat + idx) = make_float2(v0, v1);
                        if (t == TT - 1) *(float2*)(hfinal + idx) = make_float2(v0, v1);
                        *(uint32_t*)(hwh + idx) = pack2h(v0, v1);
                    }
        }

        group_sync(cntp, genp, base, gen++);
    }
}

// ---------------------------------------------------------------------------
extern "C" void kernel_launch(void* const* d_in, const int* in_sizes, int n_in,
                              void* d_out, int out_size)
{
    (void)in_sizes; (void)n_in; (void)out_size;
    const float* x  = (const float*)d_in[0];
    const float* Wx = (const float*)d_in[1];
    const float* bx = (const float*)d_in[2];
    const float* Wh = (const float*)d_in[3];
    const float* bh = (const float*)d_in[4];
    float* out = (float*)d_out;
    float* xp = out + (size_t)BB * HH;   // h_all region doubles as xp scratch

    cudaFuncSetAttribute(xproj_hmma, cudaFuncAttributeMaxDynamicSharedMemorySize, P1_SMEM);
    cudaFuncSetAttribute(rnn_hmma,  cudaFuncAttributeMaxDynamicSharedMemorySize, P2_SMEM);

    dim3 g1(HH / 128, (TT * BB) / 128);
    xproj_hmma<<<g1, 256, P1_SMEM>>>(x, Wx, bx, xp);
    rnn_hmma<<<P2_NBLK, 256, P2_SMEM>>>(Wh, bh, out);
}

// round 14
// speedup vs baseline: 1.7550x; 1.0274x over previous
#include <cuda_runtime.h>
#include <cuda_bf16.h>
#include <cuda_fp16.h>
#include <cstdint>

#define TT 512
#define BB 256
#define HH 1024
#define KK 1024

// ---------------- device globals (static scratch; no allocations) ----------
__device__ __align__(16) unsigned short g_hhi[2][BB*HH];
__device__ unsigned g_count8[8 * 32];   // one counter per bt group, 128B apart
__device__ unsigned g_gen8[8 * 32];

// ---------------- helpers ---------------------------------------------------
__device__ __forceinline__ uint32_t smem_u32(const void* p) {
    uint32_t a;
    asm("{ .reg .u64 t; cvta.to.shared.u64 t, %1; cvt.u32.u64 %0, t; }"
        : "=r"(a) : "l"(p));
    return a;
}

__device__ __forceinline__ void ldsm4(uint32_t* r, uint32_t addr) {
    asm volatile("ldmatrix.sync.aligned.m8n8.x4.shared.b16 {%0,%1,%2,%3}, [%4];"
        : "=r"(r[0]), "=r"(r[1]), "=r"(r[2]), "=r"(r[3]) : "r"(addr));
}

// fp16 MMA
__device__ __forceinline__ void mma16816h(float* c, const uint32_t* a, const uint32_t* b) {
    asm volatile("mma.sync.aligned.m16n8k16.row.col.f32.f16.f16.f32 "
        "{%0,%1,%2,%3}, {%4,%5,%6,%7}, {%8,%9}, {%0,%1,%2,%3};"
        : "+f"(c[0]), "+f"(c[1]), "+f"(c[2]), "+f"(c[3])
        : "r"(a[0]), "r"(a[1]), "r"(a[2]), "r"(a[3]), "r"(b[0]), "r"(b[1]));
}

#define CP16(dst, src) \
    asm volatile("{\n\t.reg .u64 g;\n\tcvta.to.global.u64 g, %1;\n\t" \
                 "cp.async.cg.shared.global [%0], [g], 16;\n\t}" \
                 :: "r"(dst), "l"(src) : "memory")
#define CP_COMMIT() asm volatile("cp.async.commit_group;" ::: "memory")
#define CP_WAITN(n) asm volatile("cp.async.wait_group %0;" :: "n"(n) : "memory")

#define GROUP_BAR(id) asm volatile("bar.sync %0, %1;" :: "r"(id), "r"(128) : "memory")

__device__ __forceinline__ float tanh_fast(float x) {
    float e = __expf(2.0f * x);
    return 1.0f - 2.0f / (e + 1.0f);
}

// fp16 pack
__device__ __forceinline__ uint32_t pack2h(float a, float b) {
    __half ha = __float2half_rn(a);
    __half hb = __float2half_rn(b);
    return (uint32_t)__half_as_ushort(ha) | ((uint32_t)__half_as_ushort(hb) << 16);
}

// per-bt-group barrier: 16 participating blocks
__device__ __forceinline__ void group_sync(unsigned* cntp, unsigned* genp,
                                           unsigned base, unsigned gen) {
    __syncthreads();
    if (threadIdx.x == 0) {
        const unsigned target = base + gen;
        __threadfence();
        unsigned a = atomicAdd(cntp, 1u);
        if (a == 15u) {
            *(volatile unsigned*)cntp = 0u;
            __threadfence();
            atomicExch(genp, target);
        } else {
            while ((int)(*(volatile unsigned*)genp - target) < 0) __nanosleep(32);
        }
        __threadfence();
    }
    __syncthreads();
}

// ---------------------------------------------------------------------------
// Phase 1 v3: XP = x @ Wx^T + bx, 1-term fp16, DOUBLE-BUFFERED smem
// (one __syncthreads per chunk; MMA overlaps next chunk's stores).
// ---------------------------------------------------------------------------
#define P1_A0 0
#define P1_B0 10240
#define P1_BUFSZ 20480
#define P1_SMEM 40960

__global__ void __launch_bounds__(256, 1)
xproj_hmma(const float* __restrict__ X, const float* __restrict__ Wx,
           const float* __restrict__ bx, float* __restrict__ XP)
{
    extern __shared__ char smem[];
    __shared__ float bxs[128];
    const uint32_t sb = smem_u32(smem);
    const int tid = threadIdx.x;
    const int lane = tid & 31;
    const int w = tid >> 5;
    const int wm = w >> 2;
    const int wn = w & 3;
    const int n0 = blockIdx.x * 128;
    const int m0 = blockIdx.y * 128;

    if (tid < 128) bxs[tid] = bx[n0 + tid];

    const uint32_t aRel = (uint32_t)((wm * 64 + (lane & 15)) * 80 + (lane >> 4) * 16);
    const uint32_t bRel = (uint32_t)((wn * 32 + ((lane >> 4) & 1) * 8 + (lane & 7)) * 80
                                     + ((lane >> 3) & 1) * 16);

    float cc[4][4][4];
#pragma unroll
    for (int a = 0; a < 4; ++a)
#pragma unroll
        for (int b = 0; b < 4; ++b)
#pragma unroll
            for (int q = 0; q < 4; ++q) cc[a][b][q] = 0.0f;

    float4 va[4], vb[4];
#pragma unroll
    for (int i = 0; i < 4; ++i) {
        int u = tid + 256 * i;
        int row = u >> 3, k4 = u & 7;
        va[i] = *(const float4*)(X + (size_t)(m0 + row) * KK + k4 * 4);
        vb[i] = *(const float4*)(Wx + (size_t)(n0 + row) * KK + k4 * 4);
    }

#pragma unroll 1
    for (int c = 0; c < 32; ++c) {
        const uint32_t bufOff = (uint32_t)((c & 1) * P1_BUFSZ);
#pragma unroll
        for (int i = 0; i < 4; ++i) {
            int u = tid + 256 * i;
            int row = u >> 3, k4 = u & 7;
            uint32_t off = bufOff + (uint32_t)(row * 80 + k4 * 8);
            uint2 hp;
            hp.x = pack2h(va[i].x, va[i].y);
            hp.y = pack2h(va[i].z, va[i].w);
            *(uint2*)(smem + P1_A0 + off) = hp;
            hp.x = pack2h(vb[i].x, vb[i].y);
            hp.y = pack2h(vb[i].z, vb[i].w);
            *(uint2*)(smem + P1_B0 + off) = hp;
        }
        __syncthreads();   // single sync: stores of buf[c&1] complete

        if (c < 31) {
            const int k0 = (c + 1) * 32;
#pragma unroll
            for (int i = 0; i < 4; ++i) {
                int u = tid + 256 * i;
                int row = u >> 3, k4 = u & 7;
                va[i] = *(const float4*)(X + (size_t)(m0 + row) * KK + k0 + k4 * 4);
                vb[i] = *(const float4*)(Wx + (size_t)(n0 + row) * KK + k0 + k4 * 4);
            }
        }

#pragma unroll
        for (int kk = 0; kk < 2; ++kk) {
            const uint32_t ka = kk * 32;
            uint32_t ah[4][4], bh[8];
#pragma unroll
            for (int mi = 0; mi < 4; ++mi)
                ldsm4(ah[mi], sb + P1_A0 + bufOff + aRel + mi * 1280 + ka);
            ldsm4(bh,     sb + P1_B0 + bufOff + bRel + ka);
            ldsm4(bh + 4, sb + P1_B0 + bufOff + bRel + 1280 + ka);
#pragma unroll
            for (int mi = 0; mi < 4; ++mi)
#pragma unroll
                for (int ni = 0; ni < 4; ++ni)
                    mma16816h(cc[mi][ni], ah[mi], bh + 2 * ni);
        }
        // no trailing sync: next chunk writes the other buffer
    }

#pragma unroll
    for (int mi = 0; mi < 4; ++mi)
#pragma unroll
        for (int ni = 0; ni < 4; ++ni)
#pragma unroll
            for (int p = 0; p < 2; ++p) {
                int row = wm * 64 + mi * 16 + (lane >> 2) + p * 8;
                int col = wn * 32 + ni * 8 + (lane & 3) * 2;
                float2 v;
                v.x = cc[mi][ni][2 * p]     + bxs[col];
                v.y = cc[mi][ni][2 * p + 1] + bxs[col + 1];
                *(float2*)(XP + (size_t)(m0 + row) * HH + n0 + col) = v;
            }
}

// ---------------------------------------------------------------------------
// Phase 2 v7: 1-term h product, chunk size 128 (4 chunks/kg, 4 GROUP_BARs
// per step). Stage = two 4KB k64 sub-buffers (swizzle preserved).
// 32m x 64n tile, 8 bt x 16 jt, 2 kg x 4 warps. Wh_hi resident.
// ---------------------------------------------------------------------------
#define P2_NBLK 128
#define WH_OFF  0
#define A_OFF   132096            // + kg*24576 + stage*8192 (+4096 for sub1)
#define PSM_OFF 181248            // 32 x 66 floats = 8448B
#define P2_SMEM 189696

__global__ void __launch_bounds__(256, 1)
rnn_hmma(const float* __restrict__ Wh, const float* __restrict__ bh,
         float* __restrict__ out)
{
    extern __shared__ char smem[];
    __shared__ float bhs[64];
    __shared__ unsigned sbase;
    const uint32_t sb = smem_u32(smem);
    const int tid = threadIdx.x;
    const int lane = tid & 31;
    const int w = tid >> 5;
    const int kg = w >> 2;           // k half
    const int wl = w & 3;
    const int wm = wl >> 1;          // 0..1 (16 m rows)
    const int wn = wl & 1;           // 0..1 (32 n cols)
    const int tig = tid & 127;
    const int bidx = blockIdx.x;
    const int jt = bidx & 15, bt = bidx >> 4;
    const int j0 = jt * 64, b0 = bt * 32;

    unsigned* cntp = &g_count8[bt * 32];
    unsigned* genp = &g_gen8[bt * 32];

    float* hfinal = out;
    float* hall = out + (size_t)BB * HH;
    float* psm = (float*)(smem + PSM_OFF);

    if (tid == 0) sbase = *(volatile unsigned*)genp;
    if (tid < 64) bhs[tid] = bh[j0 + tid];

    // resident Wh tile (fp16 hi): 64 j-rows x 1024 k, rows padded 2064B
#pragma unroll 1
    for (int i = tid; i < 64 * 256; i += 256) {
        int row = i >> 8, k4 = i & 255;
        float4 v = *(const float4*)(Wh + (size_t)(j0 + row) * KK + k4 * 4);
        uint2 hp;
        hp.x = pack2h(v.x, v.y);
        hp.y = pack2h(v.z, v.w);
        *(uint2*)(smem + WH_OFF + (uint32_t)(row * 2064 + k4 * 8)) = hp;
    }

    // zero this bt group's t=0 hidden-state rows (16 blocks share 32 rows)
    {
        uint4 z = make_uint4(0, 0, 0, 0);
        const int sliceBase = b0 * HH / 8;      // uint4 index of row b0
        int i = jt * 256 + tid;                 // exactly covers slice
        ((uint4*)g_hhi[0])[sliceBase + i] = z;
    }
    __syncthreads();
    const unsigned base = sbase;
    unsigned gen = 1;
    group_sync(cntp, genp, base, gen++);

    // ldmatrix A addressing (swizzled 128B rows, 32-row sub-buffer)
    const uint32_t aLin = (uint32_t)((wm * 16 + (lane & 15)) * 128 + (lane >> 4) * 16);
    const uint32_t aXor = (uint32_t)((lane & 7) << 4);
    // ldmatrix B addressing (2064B padded rows); frag f adds f*16*2064
    const uint32_t bRel = (uint32_t)((wn * 32 + ((lane >> 4) & 1) * 8 + (lane & 7)) * 2064
                                     + ((lane >> 3) & 1) * 16);
    const uint32_t kgOff = (uint32_t)(kg * 1024);   // byte offset into Wh rows
    // cp.async coords: rows cprow, cprow+16; seg cpseg; 2 subs
    const int cprow = tig >> 3, cpseg = tig & 7;
    const uint32_t aBase = sb + A_OFF + (uint32_t)(kg * 24576);
    const size_t kSrc0 = (size_t)kg * 512 + cpseg * 8;

    // epilogue fragment coordinates (local within 32x64 tile)
    int erow[2], ecol[2][2];
#pragma unroll
    for (int p = 0; p < 2; ++p) erow[p] = wm * 16 + (lane >> 2) + p * 8;
#pragma unroll
    for (int f = 0; f < 2; ++f)
#pragma unroll
        for (int ni = 0; ni < 2; ++ni)
            ecol[f][ni] = wn * 32 + f * 16 + ni * 8 + (lane & 3) * 2;

#pragma unroll 1
    for (int t = 0; t < TT; ++t) {
        const unsigned short* hrh = g_hhi[t & 1];
        unsigned short* hwh = g_hhi[(t & 1) ^ 1];
        float* hat = hall + (size_t)t * (BB * HH);

        // xp prefetch (kg0 only; consumed in epilogue)
        float2 xpv[2][2][2];
        if (kg == 0) {
#pragma unroll
            for (int f = 0; f < 2; ++f)
#pragma unroll
                for (int ni = 0; ni < 2; ++ni)
#pragma unroll
                    for (int p = 0; p < 2; ++p)
                        xpv[f][ni][p] = *(const float2*)(hat +
                            (size_t)(b0 + erow[p]) * HH + j0 + ecol[f][ni]);
        }

        float cc[2][2][4];
#pragma unroll
        for (int a = 0; a < 2; ++a)
#pragma unroll
            for (int b = 0; b < 2; ++b)
#pragma unroll
                for (int q = 0; q < 4; ++q) cc[a][b][q] = 0.0f;

        // prologue: issue chunks 0 and 1 (k128 each: 2 k64 subs)
#pragma unroll
        for (int pc = 0; pc < 2; ++pc) {
            const uint32_t stg = aBase + (uint32_t)(pc * 8192);
#pragma unroll
            for (int j = 0; j < 2; ++j) {
                int row = cprow + 16 * j;
                uint32_t off = (((uint32_t)(row * 128 + cpseg * 16)) ^ ((uint32_t)(row & 7) << 4));
                size_t src = (size_t)(b0 + row) * KK + kSrc0 + pc * 128;
                CP16(stg + off,        hrh + src);
                CP16(stg + 4096 + off, hrh + src + 64);
            }
            CP_COMMIT();
        }

#pragma unroll 1
        for (int c = 0; c < 4; ++c) {
            if (c < 3) { CP_WAITN(1); } else { CP_WAITN(0); }
            GROUP_BAR(kg + 1);
            if (c + 2 < 4) {
                const uint32_t stg = aBase + (uint32_t)(((c + 2) % 3) * 8192);
#pragma unroll
                for (int j = 0; j < 2; ++j) {
                    int row = cprow + 16 * j;
                    uint32_t off = (((uint32_t)(row * 128 + cpseg * 16)) ^ ((uint32_t)(row & 7) << 4));
                    size_t src = (size_t)(b0 + row) * KK + kSrc0 + (c + 2) * 128;
                    CP16(stg + off,        hrh + src);
                    CP16(stg + 4096 + off, hrh + src + 64);
                }
                CP_COMMIT();
            }

            const uint32_t stg = aBase + (uint32_t)((c % 3) * 8192);
            const uint32_t kOffB = kgOff + (uint32_t)(c * 256);
#pragma unroll
            for (int kk = 0; kk < 8; ++kk) {
                const uint32_t ka = (uint32_t)((kk & 3) * 32);
                const uint32_t sub = (uint32_t)((kk >> 2) * 4096);
                uint32_t ah[4], bf0[4], bf1[4];
                ldsm4(ah, stg + sub + ((aLin + ka) ^ aXor));
                ldsm4(bf0, sb + WH_OFF + bRel + kOffB + kk * 32);
                ldsm4(bf1, sb + WH_OFF + bRel + 33024 + kOffB + kk * 32);
#pragma unroll
                for (int ni = 0; ni < 2; ++ni) {
                    mma16816h(cc[0][ni], ah, bf0 + 2 * ni);
                    mma16816h(cc[1][ni], ah, bf1 + 2 * ni);
                }
            }
        }

        // kg1 publishes partials (stride 66 to avoid bank conflicts)
        if (kg == 1) {
#pragma unroll
            for (int f = 0; f < 2; ++f)
#pragma unroll
                for (int ni = 0; ni < 2; ++ni)
#pragma unroll
                    for (int p = 0; p < 2; ++p)
                        *(float2*)&psm[erow[p] * 66 + ecol[f][ni]] =
                            make_float2(cc[f][ni][2 * p], cc[f][ni][2 * p + 1]);
        }
        __syncthreads();

        // kg0 combines + epilogue
        if (kg == 0) {
#pragma unroll
            for (int f = 0; f < 2; ++f)
#pragma unroll
                for (int ni = 0; ni < 2; ++ni)
#pragma unroll
                    for (int p = 0; p < 2; ++p) {
                        const int row = erow[p], col = ecol[f][ni];
                        float2 pp = *(float2*)&psm[row * 66 + col];
                        size_t idx = (size_t)(b0 + row) * HH + j0 + col;
                        float v0 = tanh_fast(cc[f][ni][2 * p]     + pp.x + bhs[col]     + xpv[f][ni][p].x);
                        float v1 = tanh_fast(cc[f][ni][2 * p + 1] + pp.y + bhs[col + 1] + xpv[f][ni][p].y);
                        *(float2*)(hat + idx) = make_float2(v0, v1);
                        if (t == TT - 1) *(float2*)(hfinal + idx) = make_float2(v0, v1);
                        *(uint32_t*)(hwh + idx) = pack2h(v0, v1);
                    }
        }

        group_sync(cntp, genp, base, gen++);
    }
}

// ---------------------------------------------------------------------------
extern "C" void kernel_launch(void* const* d_in, const int* in_sizes, int n_in,
                              void* d_out, int out_size)
{
    (void)in_sizes; (void)n_in; (void)out_size;
    const float* x  = (const float*)d_in[0];
    const float* Wx = (const float*)d_in[1];
    const float* bx = (const float*)d_in[2];
    const float* Wh = (const float*)d_in[3];
    const float* bh = (const float*)d_in[4];
    float* out = (float*)d_out;
    float* xp = out + (size_t)BB * HH;   // h_all region doubles as xp scratch

    cudaFuncSetAttribute(xproj_hmma, cudaFuncAttributeMaxDynamicSharedMemorySize, P1_SMEM);
    cudaFuncSetAttribute(rnn_hmma,  cudaFuncAttributeMaxDynamicSharedMemorySize, P2_SMEM);

    dim3 g1(HH / 128, (TT * BB) / 128);
    xproj_hmma<<<g1, 256, P1_SMEM>>>(x, Wx, bx, xp);
    rnn_hmma<<<P2_NBLK, 256, P2_SMEM>>>(Wh, bh, out);
}

// round 16
// speedup vs baseline: 1.9151x; 1.0912x over previous
#include <cuda_runtime.h>
#include <cuda_bf16.h>
#include <cuda_fp16.h>
#include <cstdint>

#define TT 512
#define BB 256
#define HH 1024
#define KK 1024

// ---------------- device globals (static scratch; no allocations) ----------
__device__ __align__(16) unsigned short g_xh[TT*BB*HH];   // 256MB fp16(x)
__device__ __align__(16) unsigned short g_wxh[HH*KK];     // 2MB fp16(Wx)
__device__ __align__(16) unsigned short g_hhi[2][BB*HH];
__device__ unsigned g_count8[8 * 32];
__device__ unsigned g_gen8[8 * 32];

// ---------------- helpers ---------------------------------------------------
__device__ __forceinline__ uint32_t smem_u32(const void* p) {
    uint32_t a;
    asm("{ .reg .u64 t; cvta.to.shared.u64 t, %1; cvt.u32.u64 %0, t; }"
        : "=r"(a) : "l"(p));
    return a;
}

__device__ __forceinline__ void ldsm4(uint32_t* r, uint32_t addr) {
    asm volatile("ldmatrix.sync.aligned.m8n8.x4.shared.b16 {%0,%1,%2,%3}, [%4];"
        : "=r"(r[0]), "=r"(r[1]), "=r"(r[2]), "=r"(r[3]) : "r"(addr));
}

__device__ __forceinline__ void mma16816h(float* c, const uint32_t* a, const uint32_t* b) {
    asm volatile("mma.sync.aligned.m16n8k16.row.col.f32.f16.f16.f32 "
        "{%0,%1,%2,%3}, {%4,%5,%6,%7}, {%8,%9}, {%0,%1,%2,%3};"
        : "+f"(c[0]), "+f"(c[1]), "+f"(c[2]), "+f"(c[3])
        : "r"(a[0]), "r"(a[1]), "r"(a[2]), "r"(a[3]), "r"(b[0]), "r"(b[1]));
}

#define CP16(dst, src) \
    asm volatile("{\n\t.reg .u64 g;\n\tcvta.to.global.u64 g, %1;\n\t" \
                 "cp.async.cg.shared.global [%0], [g], 16;\n\t}" \
                 :: "r"(dst), "l"(src) : "memory")
#define CP_COMMIT() asm volatile("cp.async.commit_group;" ::: "memory")
#define CP_WAITN(n) asm volatile("cp.async.wait_group %0;" :: "n"(n) : "memory")

#define GROUP_BAR(id) asm volatile("bar.sync %0, %1;" :: "r"(id), "r"(128) : "memory")

__device__ __forceinline__ float tanh_fast(float x) {
    float e = __expf(2.0f * x);
    return 1.0f - 2.0f / (e + 1.0f);
}

__device__ __forceinline__ uint32_t pack2h(float a, float b) {
    __half ha = __float2half_rn(a);
    __half hb = __float2half_rn(b);
    return (uint32_t)__half_as_ushort(ha) | ((uint32_t)__half_as_ushort(hb) << 16);
}

// per-bt-group barrier: 16 participating blocks
__device__ __forceinline__ void group_sync(unsigned* cntp, unsigned* genp,
                                           unsigned base, unsigned gen) {
    __syncthreads();
    if (threadIdx.x == 0) {
        const unsigned target = base + gen;
        __threadfence();
        unsigned a = atomicAdd(cntp, 1u);
        if (a == 15u) {
            *(volatile unsigned*)cntp = 0u;
            __threadfence();
            atomicExch(genp, target);
        } else {
            while ((int)(*(volatile unsigned*)genp - target) < 0) __nanosleep(32);
        }
        __threadfence();
    }
    __syncthreads();
}

// ---------------------------------------------------------------------------
// Prep: fp32 -> fp16 conversions (bit-identical to prior in-kernel pack2h).
// ---------------------------------------------------------------------------
__global__ void xprep_kernel(const float* __restrict__ X)
{
    size_t i = (size_t)blockIdx.x * 256 + threadIdx.x;   // float4 index
    float4 v = ((const float4*)X)[i];
    uint2 hp;
    hp.x = pack2h(v.x, v.y);
    hp.y = pack2h(v.z, v.w);
    ((uint2*)g_xh)[i] = hp;
}

__global__ void wprep_kernel(const float* __restrict__ W)
{
    size_t i = (size_t)blockIdx.x * 256 + threadIdx.x;
    float4 v = ((const float4*)W)[i];
    uint2 hp;
    hp.x = pack2h(v.x, v.y);
    hp.y = pack2h(v.z, v.w);
    ((uint2*)g_wxh)[i] = hp;
}

// ---------------------------------------------------------------------------
// Phase 1 v4 (FIXED loader): XP = xh @ Wxh^T + bx. Pure cp.async 3-stage
// pipeline. Block 128m x 128n, 8 warps (64m x 32n), chunks of k64.
// Stage = A(16KB) + B(16KB); 128B rows, XOR swizzle.
// Loader: 256 threads x 4 segs x 16B = 16KB per operand per chunk (full
// coverage; R15's bug was 2 segs = half coverage -> NaN).
// ---------------------------------------------------------------------------
#define P1_STG 32768
#define P1_SMEM 98304

__global__ void __launch_bounds__(256, 1)
xproj_hmma(const float* __restrict__ bx, float* __restrict__ XP)
{
    extern __shared__ char smem[];
    __shared__ float bxs[128];
    const uint32_t sb = smem_u32(smem);
    const int tid = threadIdx.x;
    const int lane = tid & 31;
    const int w = tid >> 5;
    const int wm = w >> 2;           // 0..1 (64 m rows)
    const int wn = w & 3;            // 0..3 (32 n cols)
    const int n0 = blockIdx.x * 128;
    const int m0 = blockIdx.y * 128;

    if (tid < 128) bxs[tid] = bx[n0 + tid];
    __syncthreads();

    const uint32_t xorv = (uint32_t)((lane & 7) << 4);
    const uint32_t aLin = (uint32_t)((wm * 64 + (lane & 15)) * 128 + (lane >> 4) * 16);
    const uint32_t bLin = (uint32_t)((wn * 32 + ((lane >> 4) & 1) * 8 + (lane & 7)) * 128
                                     + ((lane >> 3) & 1) * 16);
    // cp coords: row tid>>1 (0..127), FOUR segs per thread (full row coverage)
    const int cprow = tid >> 1;
    const int cpseg0 = (tid & 1) * 4;

    float cc[4][4][4];
#pragma unroll
    for (int a = 0; a < 4; ++a)
#pragma unroll
        for (int b = 0; b < 4; ++b)
#pragma unroll
            for (int q = 0; q < 4; ++q) cc[a][b][q] = 0.0f;

    // prologue: issue chunks 0 and 1
#pragma unroll
    for (int pc = 0; pc < 2; ++pc) {
        const uint32_t stg = sb + (uint32_t)(pc * P1_STG);
#pragma unroll
        for (int i = 0; i < 4; ++i) {
            int seg = cpseg0 + i;
            uint32_t off = (uint32_t)(cprow * 128 + seg * 16) ^ ((uint32_t)(cprow & 7) << 4);
            CP16(stg + off,         g_xh  + (size_t)(m0 + cprow) * KK + pc * 64 + seg * 8);
            CP16(stg + 16384 + off, g_wxh + (size_t)(n0 + cprow) * KK + pc * 64 + seg * 8);
        }
        CP_COMMIT();
    }

#pragma unroll 1
    for (int c = 0; c < 16; ++c) {
        if (c < 15) { CP_WAITN(1); } else { CP_WAITN(0); }
        __syncthreads();
        if (c + 2 < 16) {
            const uint32_t stg = sb + (uint32_t)(((c + 2) % 3) * P1_STG);
#pragma unroll
            for (int i = 0; i < 4; ++i) {
                int seg = cpseg0 + i;
                uint32_t off = (uint32_t)(cprow * 128 + seg * 16) ^ ((uint32_t)(cprow & 7) << 4);
                size_t ks = (size_t)(c + 2) * 64 + seg * 8;
                CP16(stg + off,         g_xh  + (size_t)(m0 + cprow) * KK + ks);
                CP16(stg + 16384 + off, g_wxh + (size_t)(n0 + cprow) * KK + ks);
            }
            CP_COMMIT();
        }

        const uint32_t stg = sb + (uint32_t)((c % 3) * P1_STG);
#pragma unroll
        for (int kk = 0; kk < 4; ++kk) {
            const uint32_t ka = (uint32_t)(kk * 32);
            uint32_t ah[4][4], bh[8];
#pragma unroll
            for (int mi = 0; mi < 4; ++mi)
                ldsm4(ah[mi], stg + ((aLin + mi * 2048 + ka) ^ xorv));
            ldsm4(bh,     stg + 16384 + ((bLin + ka) ^ xorv));
            ldsm4(bh + 4, stg + 16384 + ((bLin + 2048 + ka) ^ xorv));
#pragma unroll
            for (int mi = 0; mi < 4; ++mi)
#pragma unroll
                for (int ni = 0; ni < 4; ++ni)
                    mma16816h(cc[mi][ni], ah[mi], bh + 2 * ni);
        }
    }

#pragma unroll
    for (int mi = 0; mi < 4; ++mi)
#pragma unroll
        for (int ni = 0; ni < 4; ++ni)
#pragma unroll
            for (int p = 0; p < 2; ++p) {
                int row = wm * 64 + mi * 16 + (lane >> 2) + p * 8;
                int col = wn * 32 + ni * 8 + (lane & 3) * 2;
                float2 v;
                v.x = cc[mi][ni][2 * p]     + bxs[col];
                v.y = cc[mi][ni][2 * p + 1] + bxs[col + 1];
                *(float2*)(XP + (size_t)(m0 + row) * HH + n0 + col) = v;
            }
}

// ---------------------------------------------------------------------------
// Phase 2 v8: 512 threads = 4 kg (k256 each) x 4 warps (16m x 32n).
// 2 chunks of k128 per step, both pre-issued (2 waits + 2 bars per step).
// Wh_hi resident. 32m x 64n block tile, 8 bt x 16 jt.
// ---------------------------------------------------------------------------
#define P2_NBLK 128
#define WH_OFF  0
#define A_OFF   132096            // + kg*16384 + stage*8192 (+4096 sub1)
#define PSM_OFF 197632            // 3 slabs x 32x66 floats (8448B)
#define P2_SMEM 222976

__global__ void __launch_bounds__(512, 1)
rnn_hmma(const float* __restrict__ Wh, const float* __restrict__ bh,
         float* __restrict__ out)
{
    extern __shared__ char smem[];
    __shared__ float bhs[64];
    __shared__ unsigned sbase;
    const uint32_t sb = smem_u32(smem);
    const int tid = threadIdx.x;
    const int lane = tid & 31;
    const int w = tid >> 5;
    const int kg = w >> 2;           // 0..3, k quarter
    const int wl = w & 3;
    const int wm = wl >> 1;          // 0..1 (16 m rows)
    const int wn = wl & 1;           // 0..1 (32 n cols)
    const int tig = tid & 127;
    const int bidx = blockIdx.x;
    const int jt = bidx & 15, bt = bidx >> 4;
    const int j0 = jt * 64, b0 = bt * 32;

    unsigned* cntp = &g_count8[bt * 32];
    unsigned* genp = &g_gen8[bt * 32];

    float* hfinal = out;
    float* hall = out + (size_t)BB * HH;
    float* psm = (float*)(smem + PSM_OFF);

    if (tid == 0) sbase = *(volatile unsigned*)genp;
    if (tid < 64) bhs[tid] = bh[j0 + tid];

    // resident Wh tile (fp16 hi): 64 j-rows x 1024 k, rows padded 2064B
#pragma unroll 1
    for (int i = tid; i < 64 * 256; i += 512) {
        int row = i >> 8, k4 = i & 255;
        float4 v = *(const float4*)(Wh + (size_t)(j0 + row) * KK + k4 * 4);
        uint2 hp;
        hp.x = pack2h(v.x, v.y);
        hp.y = pack2h(v.z, v.w);
        *(uint2*)(smem + WH_OFF + (uint32_t)(row * 2064 + k4 * 8)) = hp;
    }

    // zero this bt group's t=0 hidden-state rows (16 blocks share 32 rows)
    {
        uint4 z = make_uint4(0, 0, 0, 0);
        const int sliceBase = b0 * HH / 8;
        int i = jt * 512 + tid;
        if (i < 32 * HH / 8) ((uint4*)g_hhi[0])[sliceBase + i] = z;
    }
    __syncthreads();
    const unsigned base = sbase;
    unsigned gen = 1;
    group_sync(cntp, genp, base, gen++);

    // ldmatrix A addressing (swizzled 128B rows, 32-row sub-buffer)
    const uint32_t aLin = (uint32_t)((wm * 16 + (lane & 15)) * 128 + (lane >> 4) * 16);
    const uint32_t aXor = (uint32_t)((lane & 7) << 4);
    // ldmatrix B addressing (2064B padded rows)
    const uint32_t bRel = (uint32_t)((wn * 32 + ((lane >> 4) & 1) * 8 + (lane & 7)) * 2064
                                     + ((lane >> 3) & 1) * 16);
    const uint32_t kgOff = (uint32_t)(kg * 512);    // byte offset into Wh rows
    const int cprow = tig >> 3, cpseg = tig & 7;
    const uint32_t aBase = sb + A_OFF + (uint32_t)(kg * 16384);
    const size_t kSrc0 = (size_t)kg * 256 + cpseg * 8;

    // epilogue fragment coordinates (local within 32x64 tile)
    int erow[2], ecol[2][2];
#pragma unroll
    for (int p = 0; p < 2; ++p) erow[p] = wm * 16 + (lane >> 2) + p * 8;
#pragma unroll
    for (int f = 0; f < 2; ++f)
#pragma unroll
        for (int ni = 0; ni < 2; ++ni)
            ecol[f][ni] = wn * 32 + f * 16 + ni * 8 + (lane & 3) * 2;

#pragma unroll 1
    for (int t = 0; t < TT; ++t) {
        const unsigned short* hrh = g_hhi[t & 1];
        unsigned short* hwh = g_hhi[(t & 1) ^ 1];
        float* hat = hall + (size_t)t * (BB * HH);

        // xp prefetch (kg0 only; consumed in epilogue)
        float2 xpv[2][2][2];
        if (kg == 0) {
#pragma unroll
            for (int f = 0; f < 2; ++f)
#pragma unroll
                for (int ni = 0; ni < 2; ++ni)
#pragma unroll
                    for (int p = 0; p < 2; ++p)
                        xpv[f][ni][p] = *(const float2*)(hat +
                            (size_t)(b0 + erow[p]) * HH + j0 + ecol[f][ni]);
        }

        float cc[2][2][4];
#pragma unroll
        for (int a = 0; a < 2; ++a)
#pragma unroll
            for (int b = 0; b < 2; ++b)
#pragma unroll
                for (int q = 0; q < 4; ++q) cc[a][b][q] = 0.0f;

        // issue BOTH chunks (k128 each: 2 k64 subs)
#pragma unroll
        for (int pc = 0; pc < 2; ++pc) {
            const uint32_t stg = aBase + (uint32_t)(pc * 8192);
#pragma unroll
            for (int j = 0; j < 2; ++j) {
                int row = cprow + 16 * j;
                uint32_t off = (((uint32_t)(row * 128 + cpseg * 16)) ^ ((uint32_t)(row & 7) << 4));
                size_t src = (size_t)(b0 + row) * KK + kSrc0 + pc * 128;
                CP16(stg + off,        hrh + src);
                CP16(stg + 4096 + off, hrh + src + 64);
            }
            CP_COMMIT();
        }

#pragma unroll
        for (int c = 0; c < 2; ++c) {
            if (c == 0) { CP_WAITN(1); } else { CP_WAITN(0); }
            GROUP_BAR(kg + 1);

            const uint32_t stg = aBase + (uint32_t)(c * 8192);
            const uint32_t kOffB = kgOff + (uint32_t)(c * 256);
#pragma unroll
            for (int kk = 0; kk < 8; ++kk) {
                const uint32_t ka = (uint32_t)((kk & 3) * 32);
                const uint32_t sub = (uint32_t)((kk >> 2) * 4096);
                uint32_t ah[4], bf0[4], bf1[4];
                ldsm4(ah, stg + sub + ((aLin + ka) ^ aXor));
                ldsm4(bf0, sb + WH_OFF + bRel + kOffB + kk * 32);
                ldsm4(bf1, sb + WH_OFF + bRel + 33024 + kOffB + kk * 32);
#pragma unroll
                for (int ni = 0; ni < 2; ++ni) {
                    mma16816h(cc[0][ni], ah, bf0 + 2 * ni);
                    mma16816h(cc[1][ni], ah, bf1 + 2 * ni);
                }
            }
        }

        // kg1..3 publish partials (stride 66)
        if (kg != 0) {
            float* ps = psm + (kg - 1) * (32 * 66);
#pragma unroll
            for (int f = 0; f < 2; ++f)
#pragma unroll
                for (int ni = 0; ni < 2; ++ni)
#pragma unroll
                    for (int p = 0; p < 2; ++p)
                        *(float2*)&ps[erow[p] * 66 + ecol[f][ni]] =
                            make_float2(cc[f][ni][2 * p], cc[f][ni][2 * p + 1]);
        }
        __syncthreads();

        // kg0 combines + epilogue
        if (kg == 0) {
#pragma unroll
            for (int f = 0; f < 2; ++f)
#pragma unroll
                for (int ni = 0; ni < 2; ++ni)
#pragma unroll
                    for (int p = 0; p < 2; ++p) {
                        const int row = erow[p], col = ecol[f][ni];
                        float2 p1 = *(float2*)&psm[row * 66 + col];
                        float2 p2 = *(float2*)&psm[32 * 66 + row * 66 + col];
                        float2 p3 = *(float2*)&psm[64 * 66 + row * 66 + col];
                        size_t idx = (size_t)(b0 + row) * HH + j0 + col;
                        float v0 = tanh_fast(cc[f][ni][2 * p]     + p1.x + p2.x + p3.x
                                             + bhs[col]     + xpv[f][ni][p].x);
                        float v1 = tanh_fast(cc[f][ni][2 * p + 1] + p1.y + p2.y + p3.y
                                             + bhs[col + 1] + xpv[f][ni][p].y);
                        *(float2*)(hat + idx) = make_float2(v0, v1);
                        if (t == TT - 1) *(float2*)(hfinal + idx) = make_float2(v0, v1);
                        *(uint32_t*)(hwh + idx) = pack2h(v0, v1);
                    }
        }

        group_sync(cntp, genp, base, gen++);
    }
}

// ---------------------------------------------------------------------------
extern "C" void kernel_launch(void* const* d_in, const int* in_sizes, int n_in,
                              void* d_out, int out_size)
{
    (void)in_sizes; (void)n_in; (void)out_size;
    const float* x  = (const float*)d_in[0];
    const float* Wx = (const float*)d_in[1];
    const float* bx = (const float*)d_in[2];
    const float* Wh = (const float*)d_in[3];
    const float* bh = (const float*)d_in[4];
    float* out = (float*)d_out;
    float* xp = out + (size_t)BB * HH;   // h_all region doubles as xp scratch

    cudaFuncSetAttribute(xproj_hmma, cudaFuncAttributeMaxDynamicSharedMemorySize, P1_SMEM);
    cudaFuncSetAttribute(rnn_hmma,  cudaFuncAttributeMaxDynamicSharedMemorySize, P2_SMEM);

    xprep_kernel<<<(TT * BB * HH / 4) / 256, 256>>>(x);
    wprep_kernel<<<(HH * KK / 4) / 256, 256>>>(Wx);
    dim3 g1(HH / 128, (TT * BB) / 128);
    xproj_hmma<<<g1, 256, P1_SMEM>>>(bx, xp);
    rnn_hmma<<<P2_NBLK, 512, P2_SMEM>>>(Wh, bh, out);
}

// round 17
// speedup vs baseline: 1.9925x; 1.0404x over previous
#include <cuda_runtime.h>
#include <cuda_bf16.h>
#include <cuda_fp16.h>
#include <cstdint>

#define TT 512
#define BB 256
#define HH 1024
#define KK 1024

// ---------------- device globals (static scratch; no allocations) ----------
__device__ __align__(16) unsigned short g_xh[TT*BB*HH];   // 256MB fp16(x)
__device__ __align__(16) unsigned short g_wxh[HH*KK];     // 2MB fp16(Wx)
__device__ __align__(16) unsigned short g_hhi[2][BB*HH];
__device__ unsigned g_count8[8 * 32];   // one counter per bt group, 128B apart
__device__ unsigned g_gen8[8 * 32];

// ---------------- helpers ---------------------------------------------------
__device__ __forceinline__ uint32_t smem_u32(const void* p) {
    uint32_t a;
    asm("{ .reg .u64 t; cvta.to.shared.u64 t, %1; cvt.u32.u64 %0, t; }"
        : "=r"(a) : "l"(p));
    return a;
}

__device__ __forceinline__ void ldsm4(uint32_t* r, uint32_t addr) {
    asm volatile("ldmatrix.sync.aligned.m8n8.x4.shared.b16 {%0,%1,%2,%3}, [%4];"
        : "=r"(r[0]), "=r"(r[1]), "=r"(r[2]), "=r"(r[3]) : "r"(addr));
}

__device__ __forceinline__ void mma16816h(float* c, const uint32_t* a, const uint32_t* b) {
    asm volatile("mma.sync.aligned.m16n8k16.row.col.f32.f16.f16.f32 "
        "{%0,%1,%2,%3}, {%4,%5,%6,%7}, {%8,%9}, {%0,%1,%2,%3};"
        : "+f"(c[0]), "+f"(c[1]), "+f"(c[2]), "+f"(c[3])
        : "r"(a[0]), "r"(a[1]), "r"(a[2]), "r"(a[3]), "r"(b[0]), "r"(b[1]));
}

#define CP16(dst, src) \
    asm volatile("{\n\t.reg .u64 g;\n\tcvta.to.global.u64 g, %1;\n\t" \
                 "cp.async.cg.shared.global [%0], [g], 16;\n\t}" \
                 :: "r"(dst), "l"(src) : "memory")
#define CP_COMMIT() asm volatile("cp.async.commit_group;" ::: "memory")
#define CP_WAITN(n) asm volatile("cp.async.wait_group %0;" :: "n"(n) : "memory")

#define GROUP_BAR(id) asm volatile("bar.sync %0, %1;" :: "r"(id), "r"(128) : "memory")

__device__ __forceinline__ float tanh_fast(float x) {
    float e = __expf(2.0f * x);
    return 1.0f - 2.0f / (e + 1.0f);
}

__device__ __forceinline__ uint32_t pack2h(float a, float b) {
    __half ha = __float2half_rn(a);
    __half hb = __float2half_rn(b);
    return (uint32_t)__half_as_ushort(ha) | ((uint32_t)__half_as_ushort(hb) << 16);
}

// per-bt-group barrier: 16 participating blocks
__device__ __forceinline__ void group_sync(unsigned* cntp, unsigned* genp,
                                           unsigned base, unsigned gen) {
    __syncthreads();
    if (threadIdx.x == 0) {
        const unsigned target = base + gen;
        __threadfence();
        unsigned a = atomicAdd(cntp, 1u);
        if (a == 15u) {
            *(volatile unsigned*)cntp = 0u;
            __threadfence();
            atomicExch(genp, target);
        } else {
            while ((int)(*(volatile unsigned*)genp - target) < 0) __nanosleep(32);
        }
        __threadfence();
    }
    __syncthreads();
}

// ---------------------------------------------------------------------------
// Prep: fp32 -> fp16 conversions.
// ---------------------------------------------------------------------------
__global__ void xprep_kernel(const float* __restrict__ X)
{
    size_t i = (size_t)blockIdx.x * 256 + threadIdx.x;   // float4 index
    float4 v = ((const float4*)X)[i];
    uint2 hp;
    hp.x = pack2h(v.x, v.y);
    hp.y = pack2h(v.z, v.w);
    ((uint2*)g_xh)[i] = hp;
}

__global__ void wprep_kernel(const float* __restrict__ W)
{
    size_t i = (size_t)blockIdx.x * 256 + threadIdx.x;
    float4 v = ((const float4*)W)[i];
    uint2 hp;
    hp.x = pack2h(v.x, v.y);
    hp.y = pack2h(v.z, v.w);
    ((uint2*)g_wxh)[i] = hp;
}

// ---------------------------------------------------------------------------
// Phase 1 (R16 v4, measured 1.2ms incl. preps): XP = xh @ Wxh^T + bx.
// Pure cp.async 3-stage pipeline, block 128m x 128n, 8 warps (64m x 32n),
// chunks of k64. Stage = A(16KB) + B(16KB); 128B rows, XOR swizzle.
// ---------------------------------------------------------------------------
#define P1_STG 32768
#define P1_SMEM 98304

__global__ void __launch_bounds__(256, 1)
xproj_hmma(const float* __restrict__ bx, float* __restrict__ XP)
{
    extern __shared__ char smem[];
    __shared__ float bxs[128];
    const uint32_t sb = smem_u32(smem);
    const int tid = threadIdx.x;
    const int lane = tid & 31;
    const int w = tid >> 5;
    const int wm = w >> 2;           // 0..1 (64 m rows)
    const int wn = w & 3;            // 0..3 (32 n cols)
    const int n0 = blockIdx.x * 128;
    const int m0 = blockIdx.y * 128;

    if (tid < 128) bxs[tid] = bx[n0 + tid];
    __syncthreads();

    const uint32_t xorv = (uint32_t)((lane & 7) << 4);
    const uint32_t aLin = (uint32_t)((wm * 64 + (lane & 15)) * 128 + (lane >> 4) * 16);
    const uint32_t bLin = (uint32_t)((wn * 32 + ((lane >> 4) & 1) * 8 + (lane & 7)) * 128
                                     + ((lane >> 3) & 1) * 16);
    const int cprow = tid >> 1;
    const int cpseg0 = (tid & 1) * 4;

    float cc[4][4][4];
#pragma unroll
    for (int a = 0; a < 4; ++a)
#pragma unroll
        for (int b = 0; b < 4; ++b)
#pragma unroll
            for (int q = 0; q < 4; ++q) cc[a][b][q] = 0.0f;

    // prologue: issue chunks 0 and 1
#pragma unroll
    for (int pc = 0; pc < 2; ++pc) {
        const uint32_t stg = sb + (uint32_t)(pc * P1_STG);
#pragma unroll
        for (int i = 0; i < 4; ++i) {
            int seg = cpseg0 + i;
            uint32_t off = (uint32_t)(cprow * 128 + seg * 16) ^ ((uint32_t)(cprow & 7) << 4);
            CP16(stg + off,         g_xh  + (size_t)(m0 + cprow) * KK + pc * 64 + seg * 8);
            CP16(stg + 16384 + off, g_wxh + (size_t)(n0 + cprow) * KK + pc * 64 + seg * 8);
        }
        CP_COMMIT();
    }

#pragma unroll 1
    for (int c = 0; c < 16; ++c) {
        if (c < 15) { CP_WAITN(1); } else { CP_WAITN(0); }
        __syncthreads();
        if (c + 2 < 16) {
            const uint32_t stg = sb + (uint32_t)(((c + 2) % 3) * P1_STG);
#pragma unroll
            for (int i = 0; i < 4; ++i) {
                int seg = cpseg0 + i;
                uint32_t off = (uint32_t)(cprow * 128 + seg * 16) ^ ((uint32_t)(cprow & 7) << 4);
                size_t ks = (size_t)(c + 2) * 64 + seg * 8;
                CP16(stg + off,         g_xh  + (size_t)(m0 + cprow) * KK + ks);
                CP16(stg + 16384 + off, g_wxh + (size_t)(n0 + cprow) * KK + ks);
            }
            CP_COMMIT();
        }

        const uint32_t stg = sb + (uint32_t)((c % 3) * P1_STG);
#pragma unroll
        for (int kk = 0; kk < 4; ++kk) {
            const uint32_t ka = (uint32_t)(kk * 32);
            uint32_t ah[4][4], bh[8];
#pragma unroll
            for (int mi = 0; mi < 4; ++mi)
                ldsm4(ah[mi], stg + ((aLin + mi * 2048 + ka) ^ xorv));
            ldsm4(bh,     stg + 16384 + ((bLin + ka) ^ xorv));
            ldsm4(bh + 4, stg + 16384 + ((bLin + 2048 + ka) ^ xorv));
#pragma unroll
            for (int mi = 0; mi < 4; ++mi)
#pragma unroll
                for (int ni = 0; ni < 4; ++ni)
                    mma16816h(cc[mi][ni], ah[mi], bh + 2 * ni);
        }
    }

#pragma unroll
    for (int mi = 0; mi < 4; ++mi)
#pragma unroll
        for (int ni = 0; ni < 4; ++ni)
#pragma unroll
            for (int p = 0; p < 2; ++p) {
                int row = wm * 64 + mi * 16 + (lane >> 2) + p * 8;
                int col = wn * 32 + ni * 8 + (lane & 3) * 2;
                float2 v;
                v.x = cc[mi][ni][2 * p]     + bxs[col];
                v.y = cc[mi][ni][2 * p + 1] + bxs[col + 1];
                *(float2*)(XP + (size_t)(m0 + row) * HH + n0 + col) = v;
            }
}

// ---------------------------------------------------------------------------
// Phase 2 (R14 v7 verbatim — best measured at 3.22ms): 1-term h product,
// chunk size 128 (4 chunks/kg, 4 GROUP_BARs per step). Stage = two 4KB k64
// sub-buffers. 32m x 64n tile, 8 bt x 16 jt, 2 kg x 4 warps. Wh_hi resident.
// ---------------------------------------------------------------------------
#define P2_NBLK 128
#define WH_OFF  0
#define A_OFF   132096            // + kg*24576 + stage*8192 (+4096 for sub1)
#define PSM_OFF 181248            // 32 x 66 floats = 8448B
#define P2_SMEM 189696

__global__ void __launch_bounds__(256, 1)
rnn_hmma(const float* __restrict__ Wh, const float* __restrict__ bh,
         float* __restrict__ out)
{
    extern __shared__ char smem[];
    __shared__ float bhs[64];
    __shared__ unsigned sbase;
    const uint32_t sb = smem_u32(smem);
    const int tid = threadIdx.x;
    const int lane = tid & 31;
    const int w = tid >> 5;
    const int kg = w >> 2;           // k half
    const int wl = w & 3;
    const int wm = wl >> 1;          // 0..1 (16 m rows)
    const int wn = wl & 1;           // 0..1 (32 n cols)
    const int tig = tid & 127;
    const int bidx = blockIdx.x;
    const int jt = bidx & 15, bt = bidx >> 4;
    const int j0 = jt * 64, b0 = bt * 32;

    unsigned* cntp = &g_count8[bt * 32];
    unsigned* genp = &g_gen8[bt * 32];

    float* hfinal = out;
    float* hall = out + (size_t)BB * HH;
    float* psm = (float*)(smem + PSM_OFF);

    if (tid == 0) sbase = *(volatile unsigned*)genp;
    if (tid < 64) bhs[tid] = bh[j0 + tid];

    // resident Wh tile (fp16 hi): 64 j-rows x 1024 k, rows padded 2064B
#pragma unroll 1
    for (int i = tid; i < 64 * 256; i += 256) {
        int row = i >> 8, k4 = i & 255;
        float4 v = *(const float4*)(Wh + (size_t)(j0 + row) * KK + k4 * 4);
        uint2 hp;
        hp.x = pack2h(v.x, v.y);
        hp.y = pack2h(v.z, v.w);
        *(uint2*)(smem + WH_OFF + (uint32_t)(row * 2064 + k4 * 8)) = hp;
    }

    // zero this bt group's t=0 hidden-state rows (16 blocks share 32 rows)
    {
        uint4 z = make_uint4(0, 0, 0, 0);
        const int sliceBase = b0 * HH / 8;      // uint4 index of row b0
        int i = jt * 256 + tid;                 // exactly covers slice
        ((uint4*)g_hhi[0])[sliceBase + i] = z;
    }
    __syncthreads();
    const unsigned base = sbase;
    unsigned gen = 1;
    group_sync(cntp, genp, base, gen++);

    // ldmatrix A addressing (swizzled 128B rows, 32-row sub-buffer)
    const uint32_t aLin = (uint32_t)((wm * 16 + (lane & 15)) * 128 + (lane >> 4) * 16);
    const uint32_t aXor = (uint32_t)((lane & 7) << 4);
    // ldmatrix B addressing (2064B padded rows); frag f adds f*16*2064
    const uint32_t bRel = (uint32_t)((wn * 32 + ((lane >> 4) & 1) * 8 + (lane & 7)) * 2064
                                     + ((lane >> 3) & 1) * 16);
    const uint32_t kgOff = (uint32_t)(kg * 1024);   // byte offset into Wh rows
    const int cprow = tig >> 3, cpseg = tig & 7;
    const uint32_t aBase = sb + A_OFF + (uint32_t)(kg * 24576);
    const size_t kSrc0 = (size_t)kg * 512 + cpseg * 8;

    // epilogue fragment coordinates (local within 32x64 tile)
    int erow[2], ecol[2][2];
#pragma unroll
    for (int p = 0; p < 2; ++p) erow[p] = wm * 16 + (lane >> 2) + p * 8;
#pragma unroll
    for (int f = 0; f < 2; ++f)
#pragma unroll
        for (int ni = 0; ni < 2; ++ni)
            ecol[f][ni] = wn * 32 + f * 16 + ni * 8 + (lane & 3) * 2;

#pragma unroll 1
    for (int t = 0; t < TT; ++t) {
        const unsigned short* hrh = g_hhi[t & 1];
        unsigned short* hwh = g_hhi[(t & 1) ^ 1];
        float* hat = hall + (size_t)t * (BB * HH);

        // xp prefetch (kg0 only; consumed in epilogue)
        float2 xpv[2][2][2];
        if (kg == 0) {
#pragma unroll
            for (int f = 0; f < 2; ++f)
#pragma unroll
                for (int ni = 0; ni < 2; ++ni)
#pragma unroll
                    for (int p = 0; p < 2; ++p)
                        xpv[f][ni][p] = *(const float2*)(hat +
                            (size_t)(b0 + erow[p]) * HH + j0 + ecol[f][ni]);
        }

        float cc[2][2][4];
#pragma unroll
        for (int a = 0; a < 2; ++a)
#pragma unroll
            for (int b = 0; b < 2; ++b)
#pragma unroll
                for (int q = 0; q < 4; ++q) cc[a][b][q] = 0.0f;

        // prologue: issue chunks 0 and 1 (k128 each: 2 k64 subs)
#pragma unroll
        for (int pc = 0; pc < 2; ++pc) {
            const uint32_t stg = aBase + (uint32_t)(pc * 8192);
#pragma unroll
            for (int j = 0; j < 2; ++j) {
                int row = cprow + 16 * j;
                uint32_t off = (((uint32_t)(row * 128 + cpseg * 16)) ^ ((uint32_t)(row & 7) << 4));
                size_t src = (size_t)(b0 + row) * KK + kSrc0 + pc * 128;
                CP16(stg + off,        hrh + src);
                CP16(stg + 4096 + off, hrh + src + 64);
            }
            CP_COMMIT();
        }

#pragma unroll 1
        for (int c = 0; c < 4; ++c) {
            if (c < 3) { CP_WAITN(1); } else { CP_WAITN(0); }
            GROUP_BAR(kg + 1);
            if (c + 2 < 4) {
                const uint32_t stg = aBase + (uint32_t)(((c + 2) % 3) * 8192);
#pragma unroll
                for (int j = 0; j < 2; ++j) {
                    int row = cprow + 16 * j;
                    uint32_t off = (((uint32_t)(row * 128 + cpseg * 16)) ^ ((uint32_t)(row & 7) << 4));
                    size_t src = (size_t)(b0 + row) * KK + kSrc0 + (c + 2) * 128;
                    CP16(stg + off,        hrh + src);
                    CP16(stg + 4096 + off, hrh + src + 64);
                }
                CP_COMMIT();
            }

            const uint32_t stg = aBase + (uint32_t)((c % 3) * 8192);
            const uint32_t kOffB = kgOff + (uint32_t)(c * 256);
#pragma unroll
            for (int kk = 0; kk < 8; ++kk) {
                const uint32_t ka = (uint32_t)((kk & 3) * 32);
                const uint32_t sub = (uint32_t)((kk >> 2) * 4096);
                uint32_t ah[4], bf0[4], bf1[4];
                ldsm4(ah, stg + sub + ((aLin + ka) ^ aXor));
                ldsm4(bf0, sb + WH_OFF + bRel + kOffB + kk * 32);
                ldsm4(bf1, sb + WH_OFF + bRel + 33024 + kOffB + kk * 32);
#pragma unroll
                for (int ni = 0; ni < 2; ++ni) {
                    mma16816h(cc[0][ni], ah, bf0 + 2 * ni);
                    mma16816h(cc[1][ni], ah, bf1 + 2 * ni);
                }
            }
        }

        // kg1 publishes partials (stride 66 to avoid bank conflicts)
        if (kg == 1) {
#pragma unroll
            for (int f = 0; f < 2; ++f)
#pragma unroll
                for (int ni = 0; ni < 2; ++ni)
#pragma unroll
                    for (int p = 0; p < 2; ++p)
                        *(float2*)&psm[erow[p] * 66 + ecol[f][ni]] =
                            make_float2(cc[f][ni][2 * p], cc[f][ni][2 * p + 1]);
        }
        __syncthreads();

        // kg0 combines + epilogue
        if (kg == 0) {
#pragma unroll
            for (int f = 0; f < 2; ++f)
#pragma unroll
                for (int ni = 0; ni < 2; ++ni)
#pragma unroll
                    for (int p = 0; p < 2; ++p) {
                        const int row = erow[p], col = ecol[f][ni];
                        float2 pp = *(float2*)&psm[row * 66 + col];
                        size_t idx = (size_t)(b0 + row) * HH + j0 + col;
                        float v0 = tanh_fast(cc[f][ni][2 * p]     + pp.x + bhs[col]     + xpv[f][ni][p].x);
                        float v1 = tanh_fast(cc[f][ni][2 * p + 1] + pp.y + bhs[col + 1] + xpv[f][ni][p].y);
                        *(float2*)(hat + idx) = make_float2(v0, v1);
                        if (t == TT - 1) *(float2*)(hfinal + idx) = make_float2(v0, v1);
                        *(uint32_t*)(hwh + idx) = pack2h(v0, v1);
                    }
        }

        group_sync(cntp, genp, base, gen++);
    }
}

// ---------------------------------------------------------------------------
extern "C" void kernel_launch(void* const* d_in, const int* in_sizes, int n_in,
                              void* d_out, int out_size)
{
    (void)in_sizes; (void)n_in; (void)out_size;
    const float* x  = (const float*)d_in[0];
    const float* Wx = (const float*)d_in[1];
    const float* bx = (const float*)d_in[2];
    const float* Wh = (const float*)d_in[3];
    const float* bh = (const float*)d_in[4];
    float* out = (float*)d_out;
    float* xp = out + (size_t)BB * HH;   // h_all region doubles as xp scratch

    cudaFuncSetAttribute(xproj_hmma, cudaFuncAttributeMaxDynamicSharedMemorySize, P1_SMEM);
    cudaFuncSetAttribute(rnn_hmma,  cudaFuncAttributeMaxDynamicSharedMemorySize, P2_SMEM);

    xprep_kernel<<<(TT * BB * HH / 4) / 256, 256>>>(x);
    wprep_kernel<<<(HH * KK / 4) / 256, 256>>>(Wx);
    dim3 g1(HH / 128, (TT * BB) / 128);
    xproj_hmma<<<g1, 256, P1_SMEM>>>(bx, xp);
    rnn_hmma<<<P2_NBLK, 256, P2_SMEM>>>(Wh, bh, out);
}